// round 11
// baseline (speedup 1.0000x reference)
#include <cuda_runtime.h>
#include <cuda_bf16.h>
#include <math.h>
#include <stdint.h>

// Problem constants
#define NROWS 512      // B*N = 16*32
#define NO 128         // node out dim
#define EH 256         // edge/node hidden dim
#define TSTEPS 25
#define GRID 128       // persistent CTAs (<= 148 SMs -> all resident)

// Scratch (device globals: no allocation allowed)
__device__ float g_x[NROWS * NO];        // node features / GRU hidden
__device__ float g_P[NROWS * EH];        // x @ W1_top   (send half)
__device__ float g_Q[NROWS * EH];        // x @ W1_bot   (rec half)
__device__ float g_msg[NROWS * NO];      // edge2node mean message
__device__ uint32_t g_Whi[2][128 * 128]; // edge W2 bf16-hi, k-pair packed
__device__ uint32_t g_Wlo[2][128 * 128]; // edge W2 bf16-lo
__device__ float g_WgT[6][128 * 128];    // GRU gates [ir,ii,in,hr,hi,hn]: [c][k]
__device__ float g_W1nT[256 * 256];      // de_w1 transposed: [j][k]
__device__ float g_Wpe1T[256 * 256];     // pe_w1 transposed: [j][k]

// ---------------------------------------------------------------------------
// Software grid barrier (all GRID CTAs resident by construction).
// __threadfence() orders prior writes AND flushes L1D (CCTL.IVALL on sm_103a),
// so post-barrier plain loads cannot hit stale L1 lines.
// ---------------------------------------------------------------------------
__device__ unsigned g_bar_arrive = 0;
__device__ volatile unsigned g_bar_gen = 0;

__device__ __forceinline__ void grid_sync(unsigned &gen) {
    __threadfence();
    __syncthreads();
    if (threadIdx.x == 0) {
        unsigned old = atomicInc(&g_bar_arrive, GRID - 1);
        if (old == GRID - 1) {
            g_bar_gen = gen + 1;          // release (counter auto-wrapped to 0)
        } else {
            while (g_bar_gen == gen) { }  // volatile spin
        }
    }
    __syncthreads();
    gen++;
}

__device__ __forceinline__ float dot4(float acc, float4 a, float4 b) {
    acc = fmaf(a.x, b.x, acc);
    acc = fmaf(a.y, b.y, acc);
    acc = fmaf(a.z, b.z, acc);
    acc = fmaf(a.w, b.w, acc);
    return acc;
}

__device__ __forceinline__ void mma_bf16(float (&d)[4], const uint32_t (&a)[4],
                                         uint32_t b0, uint32_t b1)
{
    asm volatile(
        "mma.sync.aligned.m16n8k16.row.col.f32.bf16.bf16.f32 "
        "{%0,%1,%2,%3}, {%4,%5,%6,%7}, {%8,%9}, {%0,%1,%2,%3};"
        : "+f"(d[0]), "+f"(d[1]), "+f"(d[2]), "+f"(d[3])
        : "r"(a[0]), "r"(a[1]), "r"(a[2]), "r"(a[3]), "r"(b0), "r"(b1));
}

// Shared memory layout (u32 units): sA[2][128][132] | sB[2][32][136] | qb[4*256] | red[8*128]
#define SMEM_U32 (2*128*132 + 2*32*136 + 1024 + 1024)
#define SMEM_BYTES (SMEM_U32 * 4)

// ---------------------------------------------------------------------------
// Edge phase: CTA handles b = cta>>3, receivers r0..r0+3 (r0 = (cta&7)*4).
// M = 128 rows (4 recv x 32 send), N = 128, K = 256, bf16 hi/lo (3 MMAs).
// Warp w owns rows w*16..w*16+15 and ALL 128 cols (j = 0..15).
// ---------------------------------------------------------------------------
__device__ void edge_phase(int cta, int tid, int mat,
                           const float* __restrict__ b1,
                           const float* __restrict__ b2, uint32_t* sm)
{
    uint32_t* sA = sm;                          // hi [128][132], lo at +128*132
    uint32_t* sB = sm + 2 * 128 * 132;          // [2][32][136]
    float*    qb = (float*)(sB + 2 * 32 * 136); // [4][256]
    float*    red = qb + 4 * 256;               // [8][128]

    const int b   = cta >> 3;
    const int r0  = (cta & 7) * 4;
    const int bn0 = b * 32 + r0;

    // qb[r][k] = Q[bn0+r][k] + b1[k]
#pragma unroll
    for (int i = 0; i < 4; i++) {
        int idx = tid + i * 256;
        int r = idx >> 8, k = idx & 255;
        qb[idx] = g_Q[(bn0 + r) * EH + k] + b1[k];
    }
    __syncthreads();

    // Build A (bf16 hi/lo, packed k-pairs): 128 rows x 128 pairs
#pragma unroll 4
    for (int i = 0; i < 64; i++) {
        int lin = tid + i * 256;
        int row = lin >> 7, kp = lin & 127;
        int recv = row >> 5, send = row & 31;
        float2 p = *(const float2*)(g_P + (b * 32 + send) * EH + 2 * kp);
        float2 q = *(const float2*)(qb + recv * 256 + 2 * kp);
        float a0 = fmaxf(p.x + q.x, 0.f);
        float a1 = fmaxf(p.y + q.y, 0.f);
        __nv_bfloat162 h2 = __floats2bfloat162_rn(a0, a1);
        float l0 = a0 - __low2float(h2);
        float l1 = a1 - __high2float(h2);
        __nv_bfloat162 l2 = __floats2bfloat162_rn(l0, l1);
        sA[row * 132 + kp]             = *reinterpret_cast<uint32_t*>(&h2);
        sA[128 * 132 + row * 132 + kp] = *reinterpret_cast<uint32_t*>(&l2);
    }
    __syncthreads();

    const int lane = tid & 31;
    const int warp = tid >> 5;
    const int g    = lane >> 2;
    const int tg   = lane & 3;
    const int lrow = warp * 16 + (lane & 7) + ((lane >> 3) & 1) * 8;
    const int lkof = ((lane >> 4) & 1) * 4;
    const uint32_t sA_base = (uint32_t)__cvta_generic_to_shared(sA);

    float d[16][4];
#pragma unroll
    for (int j = 0; j < 16; j++)
#pragma unroll
        for (int r = 0; r < 4; r++) d[j][r] = 0.f;

    const uint32_t* gWhi = g_Whi[mat];
    const uint32_t* gWlo = g_Wlo[mat];

    for (int ch = 0; ch < 4; ch++) {
        // stage B chunk (32 kpairs x 128 cols, hi+lo) cooperatively
#pragma unroll
        for (int i = 0; i < 8; i++) {
            int lin = tid + i * 256;
            int split = lin >> 10;
            int rem = lin & 1023;
            int r = rem >> 5, c4 = rem & 31;
            const uint4* src = (const uint4*)((split ? gWlo : gWhi) + ch * 32 * 128);
            *(uint4*)(sB + split * 4352 + r * 136 + c4 * 4) = src[r * 32 + c4];
        }
        __syncthreads();

#pragma unroll
        for (int t = 0; t < 4; t++) {
            const int kq = (ch * 4 + t) * 8;
            uint32_t ah[4], al[4];
            {
                uint32_t addr = sA_base + (uint32_t)(lrow * 132 + kq + lkof) * 4u;
                asm volatile("ldmatrix.sync.aligned.m8n8.x4.shared.b16 {%0,%1,%2,%3}, [%4];"
                    : "=r"(ah[0]), "=r"(ah[1]), "=r"(ah[2]), "=r"(ah[3]) : "r"(addr));
                addr += 128u * 132u * 4u;
                asm volatile("ldmatrix.sync.aligned.m8n8.x4.shared.b16 {%0,%1,%2,%3}, [%4];"
                    : "=r"(al[0]), "=r"(al[1]), "=r"(al[2]), "=r"(al[3]) : "r"(addr));
            }
            const int rb0 = (t * 8 + tg) * 136;
            const int rb1 = (t * 8 + 4 + tg) * 136;
#pragma unroll
            for (int j = 0; j < 16; j++) {
                int col = j * 8 + g;
                uint32_t bh0 = sB[rb0 + col];
                uint32_t bh1 = sB[rb1 + col];
                uint32_t bl0 = sB[4352 + rb0 + col];
                uint32_t bl1 = sB[4352 + rb1 + col];
                mma_bf16(d[j], ah, bh0, bh1);
                mma_bf16(d[j], al, bh0, bh1);
                mma_bf16(d[j], ah, bl0, bl1);
            }
        }
        __syncthreads();
    }

    // Epilogue: bias + ReLU + self-edge exclusion + sender-sum
    const int recvL = warp >> 1;
    const int nrecv = r0 + recvL;                 // joint index of this receiver
    const int sendA = (warp & 1) * 16 + g;
    const int sendB = sendA + 8;
    float t0[16], t1[16];
#pragma unroll
    for (int j = 0; j < 16; j++) {
        int c0 = j * 8 + 2 * tg;
        float bb0 = b2[c0], bb1 = b2[c0 + 1];
        float v00 = fmaxf(d[j][0] + bb0, 0.f);
        float v01 = fmaxf(d[j][1] + bb1, 0.f);
        float v10 = fmaxf(d[j][2] + bb0, 0.f);
        float v11 = fmaxf(d[j][3] + bb1, 0.f);
        if (sendA == nrecv) { v00 = 0.f; v01 = 0.f; }
        if (sendB == nrecv) { v10 = 0.f; v11 = 0.f; }
        t0[j] = v00 + v10;
        t1[j] = v01 + v11;
    }
#pragma unroll
    for (int off = 4; off < 32; off <<= 1) {
#pragma unroll
        for (int j = 0; j < 16; j++) {
            t0[j] += __shfl_xor_sync(0xffffffffu, t0[j], off);
            t1[j] += __shfl_xor_sync(0xffffffffu, t1[j], off);
        }
    }
    if (lane < 4) {
#pragma unroll
        for (int j = 0; j < 16; j++) {
            int c0 = j * 8 + 2 * lane;
            red[warp * 128 + c0]     = t0[j];
            red[warp * 128 + c0 + 1] = t1[j];
        }
    }
    __syncthreads();
#pragma unroll
    for (int i = 0; i < 2; i++) {
        int idx = tid + i * 256;            // 4 recv x 128 cols
        int rv = idx >> 7, c = idx & 127;
        g_msg[(bn0 + rv) * 128 + c] =
            (red[(2 * rv) * 128 + c] + red[(2 * rv + 1) * 128 + c]) * (1.0f / 31.0f);
    }
}

// ---------------------------------------------------------------------------
// MLP phase (encoder mlp1 / passing node MLP) + next-stage P/Q. 4 rows/CTA.
// ---------------------------------------------------------------------------
template<int K1>
__device__ void mlp_phase(int cta, int tid, const float* __restrict__ in,
                          const float* __restrict__ w1, const float* __restrict__ b1,
                          const float* __restrict__ w2, const float* __restrict__ b2,
                          const float* __restrict__ WT, uint32_t* sm)
{
    float* in_s = (float*)sm;          // [4][K1]
    float* hid  = in_s + 4 * K1;       // [4][256]
    float* xs   = hid + 4 * 256;       // [4][128]

    const int row0 = cta * 4;
    for (int idx = tid; idx < 4 * K1; idx += 256)
        in_s[idx] = in[row0 * K1 + idx];
    __syncthreads();

    // layer 1: K1 -> 256
    {
        const int j = tid;
        float acc[4] = {0.f, 0.f, 0.f, 0.f};
#pragma unroll 8
        for (int k = 0; k < K1; k++) {
            float w = w1[k * EH + j];
#pragma unroll
            for (int r = 0; r < 4; r++) acc[r] = fmaf(in_s[r * K1 + k], w, acc[r]);
        }
        float bb = b1[j];
#pragma unroll
        for (int r = 0; r < 4; r++) hid[r * 256 + j] = fmaxf(acc[r] + bb, 0.f);
    }
    __syncthreads();

    // layer 2: 256 -> 128
    {
        const int c = tid & 127, g2 = tid >> 7;
        float acc[2] = {0.f, 0.f};
#pragma unroll 8
        for (int k = 0; k < EH; k++) {
            float w = w2[k * NO + c];
#pragma unroll
            for (int r = 0; r < 2; r++) acc[r] = fmaf(hid[(g2 * 2 + r) * 256 + k], w, acc[r]);
        }
        float bb = b2[c];
#pragma unroll
        for (int r = 0; r < 2; r++) {
            float o = fmaxf(acc[r] + bb, 0.f);
            xs[(g2 * 2 + r) * 128 + c] = o;
            g_x[(row0 + g2 * 2 + r) * NO + c] = o;
        }
    }
    __syncthreads();

    // next-stage P/Q via transposed weights (float4 per-thread loads)
    {
        const int j = tid;
        const float4* Wp = (const float4*)(WT + j * 256);
        const float4* Wq = (const float4*)(WT + j * 256 + 128);
        float accP[4] = {0,0,0,0}, accQ[4] = {0,0,0,0};
#pragma unroll 2
        for (int k4 = 0; k4 < 32; k4++) {
            float4 wp = Wp[k4];
            float4 wq = Wq[k4];
#pragma unroll
            for (int r = 0; r < 4; r++) {
                float4 x = ((const float4*)(xs + r * 128))[k4];
                accP[r] = dot4(accP[r], x, wp);
                accQ[r] = dot4(accQ[r], x, wq);
            }
        }
#pragma unroll
        for (int r = 0; r < 4; r++) {
            g_P[(row0 + r) * EH + j] = accP[r];
            g_Q[(row0 + r) * EH + j] = accQ[r];
        }
    }
}

// ---------------------------------------------------------------------------
// GRU phase: 4 rows/CTA, fused next-step P/Q (de_w1 transposed).
// ---------------------------------------------------------------------------
__device__ void gru_phase(int cta, int tid, const float* __restrict__ dec_t,
    const float* __restrict__ w_ir, const float* __restrict__ b_ir,
    const float* __restrict__ w_ii, const float* __restrict__ b_ii,
    const float* __restrict__ w_in, const float* __restrict__ b_in,
    float* __restrict__ out_t, float* __restrict__ state, uint32_t* sm)
{
    float* m_s  = (float*)sm;      // [4][128]
    float* h_s  = m_s + 4 * 128;   // [4][128]
    float* hn_s = h_s + 4 * 128;   // [4][128]
    float* inp_s = hn_s + 4 * 128; // [4][3]

    const int row0 = cta * 4;
#pragma unroll
    for (int i = 0; i < 2; i++) {
        int idx = tid + i * 256;
        int r = idx >> 7, k = idx & 127;
        m_s[r * 128 + k] = g_msg[(row0 + r) * NO + k];
        h_s[r * 128 + k] = g_x[(row0 + r) * NO + k];
    }
    if (tid < 12) {
        int r = tid / 3, j = tid - r * 3;
        inp_s[r * 3 + j] = dec_t[(row0 + r) * 3 + j];
    }
    __syncthreads();

    const int c = tid & 127, g2 = tid >> 7;
    float a[6][2];
#pragma unroll
    for (int g = 0; g < 6; g++) { a[g][0] = 0.f; a[g][1] = 0.f; }

    const float4* W0 = (const float4*)(g_WgT[0] + c * 128);
    const float4* W1 = (const float4*)(g_WgT[1] + c * 128);
    const float4* W2 = (const float4*)(g_WgT[2] + c * 128);
    const float4* W3 = (const float4*)(g_WgT[3] + c * 128);
    const float4* W4 = (const float4*)(g_WgT[4] + c * 128);
    const float4* W5 = (const float4*)(g_WgT[5] + c * 128);

#pragma unroll 2
    for (int k4 = 0; k4 < 32; k4++) {
        float4 wir = W0[k4], wii = W1[k4], win = W2[k4];
        float4 whr = W3[k4], whi = W4[k4], whn = W5[k4];
#pragma unroll
        for (int r = 0; r < 2; r++) {
            float4 m = ((const float4*)(m_s + (g2 * 2 + r) * 128))[k4];
            float4 h = ((const float4*)(h_s + (g2 * 2 + r) * 128))[k4];
            a[0][r] = dot4(a[0][r], m, wir);
            a[1][r] = dot4(a[1][r], m, wii);
            a[2][r] = dot4(a[2][r], m, win);
            a[3][r] = dot4(a[3][r], h, whr);
            a[4][r] = dot4(a[4][r], h, whi);
            a[5][r] = dot4(a[5][r], h, whn);
        }
    }
#pragma unroll
    for (int j = 0; j < 3; j++) {
        float wirv = w_ir[(128 + j) * 128 + c];
        float wiiv = w_ii[(128 + j) * 128 + c];
        float winv = w_in[(128 + j) * 128 + c];
#pragma unroll
        for (int r = 0; r < 2; r++) {
            float x = inp_s[(g2 * 2 + r) * 3 + j];
            a[0][r] = fmaf(x, wirv, a[0][r]);
            a[1][r] = fmaf(x, wiiv, a[1][r]);
            a[2][r] = fmaf(x, winv, a[2][r]);
        }
    }

    float bir = b_ir[c], bii = b_ii[c], bin = b_in[c];
#pragma unroll
    for (int r = 0; r < 2; r++) {
        int row = g2 * 2 + r;
        float rr = 1.f / (1.f + expf(-(a[0][r] + bir + a[3][r])));
        float ii = 1.f / (1.f + expf(-(a[1][r] + bii + a[4][r])));
        float nn = tanhf(a[2][r] + bin + rr * a[5][r]);
        float hv = (1.f - ii) * nn + ii * h_s[row * 128 + c];
        hn_s[row * 128 + c] = hv;
        int grow = row0 + row;
        g_x[grow * NO + c] = hv;
        out_t[grow * NO + c] = hv;
        if (state) state[grow * NO + c] = hv;
    }
    __syncthreads();

    // fused next-step P/Q from h'
    {
        const int j = tid;
        const float4* Wp = (const float4*)(g_W1nT + j * 256);
        const float4* Wq = (const float4*)(g_W1nT + j * 256 + 128);
        float accP[4] = {0,0,0,0}, accQ[4] = {0,0,0,0};
#pragma unroll 2
        for (int k4 = 0; k4 < 32; k4++) {
            float4 wp = Wp[k4];
            float4 wq = Wq[k4];
#pragma unroll
            for (int r = 0; r < 4; r++) {
                float4 x = ((const float4*)(hn_s + r * 128))[k4];
                accP[r] = dot4(accP[r], x, wp);
                accQ[r] = dot4(accQ[r], x, wq);
            }
        }
#pragma unroll
        for (int r = 0; r < 4; r++) {
            g_P[(row0 + r) * EH + j] = accP[r];
            g_Q[(row0 + r) * EH + j] = accQ[r];
        }
    }
}

// ---------------------------------------------------------------------------
// Single persistent kernel: pack -> encoder -> 2 passing rounds -> 25 GRU steps
// ---------------------------------------------------------------------------
__global__ __launch_bounds__(256, 1) void fused_kernel(
    const float* __restrict__ enc_in, const float* __restrict__ dec_in,
    const float* __restrict__ enc_w1, const float* __restrict__ enc_b1,
    const float* __restrict__ enc_w2, const float* __restrict__ enc_b2,
    const float* __restrict__ pe_w1,  const float* __restrict__ pe_b1,
    const float* __restrict__ pe_w2,  const float* __restrict__ pe_b2,
    const float* __restrict__ pn_w1,  const float* __restrict__ pn_b1,
    const float* __restrict__ pn_w2,  const float* __restrict__ pn_b2,
    const float* __restrict__ de_w1,  const float* __restrict__ de_b1,
    const float* __restrict__ de_w2,  const float* __restrict__ de_b2,
    const float* __restrict__ w_hr, const float* __restrict__ w_hi,
    const float* __restrict__ w_hn,
    const float* __restrict__ w_ir, const float* __restrict__ b_ir,
    const float* __restrict__ w_ii, const float* __restrict__ b_ii,
    const float* __restrict__ w_in, const float* __restrict__ b_in,
    float* __restrict__ out, float* __restrict__ state)
{
    extern __shared__ uint32_t sm[];
    const int cta = blockIdx.x;
    const int tid = threadIdx.x;
    unsigned gen = g_bar_gen;   // same initial value for all threads (no writers yet)

    // ---- phase 0: weight packing (32768 threads) ----
    {
        int idx = cta * 256 + tid;   // 0..32767
        // edge W2 hi/lo pack (2 mats x 16384)
        {
            int mat = idx >> 14, rem = idx & 16383;
            int r = rem >> 7, n = rem & 127;
            const float* W = mat ? de_w2 : pe_w2;
            float w0 = W[(2 * r) * 128 + n];
            float w1 = W[(2 * r + 1) * 128 + n];
            __nv_bfloat162 h2 = __floats2bfloat162_rn(w0, w1);
            float l0 = w0 - __low2float(h2);
            float l1 = w1 - __high2float(h2);
            __nv_bfloat162 l2 = __floats2bfloat162_rn(l0, l1);
            g_Whi[mat][r * 128 + n] = *reinterpret_cast<uint32_t*>(&h2);
            g_Wlo[mat][r * 128 + n] = *reinterpret_cast<uint32_t*>(&l2);
        }
        // GRU gate transposes (6 x 16384 = 3 x 32768)
#pragma unroll
        for (int i = 0; i < 3; i++) {
            int t = idx + i * 32768;
            int g = t >> 14, rem = t & 16383;
            int c = rem >> 7, k = rem & 127;
            const float* W;
            switch (g) {
                case 0: W = w_ir; break; case 1: W = w_ii; break;
                case 2: W = w_in; break; case 3: W = w_hr; break;
                case 4: W = w_hi; break; default: W = w_hn; break;
            }
            g_WgT[g][c * 128 + k] = W[k * 128 + c];
        }
        // de_w1 / pe_w1 transposes (65536 each)
#pragma unroll
        for (int i = 0; i < 2; i++) {
            int t = idx + i * 32768;
            int j = t >> 8, k = t & 255;
            g_W1nT[t]  = de_w1[k * 256 + j];
            g_Wpe1T[t] = pe_w1[k * 256 + j];
        }
    }
    grid_sync(gen);

    // ---- encoder mlp1 + P/Q for pass round 1 ----
    mlp_phase<150>(cta, tid, enc_in, enc_w1, enc_b1, enc_w2, enc_b2, g_Wpe1T, sm);
    grid_sync(gen);

    // ---- two message-passing rounds ----
    for (int p = 0; p < 2; p++) {
        edge_phase(cta, tid, 0, pe_b1, pe_b2, sm);
        grid_sync(gen);
        mlp_phase<128>(cta, tid, g_msg, pn_w1, pn_b1, pn_w2, pn_b2,
                       (p == 0) ? g_Wpe1T : g_W1nT, sm);
        grid_sync(gen);
    }

    // ---- decoder: 25 GRU steps ----
    for (int t = 0; t < TSTEPS; t++) {
        edge_phase(cta, tid, 1, de_b1, de_b2, sm);
        grid_sync(gen);
        gru_phase(cta, tid, dec_in + (size_t)t * NROWS * 3,
                  w_ir, b_ir, w_ii, b_ii, w_in, b_in,
                  out + (size_t)t * NROWS * NO,
                  (t == TSTEPS - 1) ? state : nullptr, sm);
        grid_sync(gen);
    }
}

// ---------------------------------------------------------------------------
extern "C" void kernel_launch(void* const* d_in, const int* in_sizes, int n_in,
                              void* d_out, int out_size)
{
    const float* enc_in = (const float*)d_in[0];
    const float* dec_in = (const float*)d_in[1];
    // d_in[2]=rec_encode, d_in[3]=send_encode (structure hardcoded)
    const float* enc_w1 = (const float*)d_in[4];
    const float* enc_b1 = (const float*)d_in[5];
    const float* enc_w2 = (const float*)d_in[6];
    const float* enc_b2 = (const float*)d_in[7];
    const float* pe_w1  = (const float*)d_in[8];
    const float* pe_b1  = (const float*)d_in[9];
    const float* pe_w2  = (const float*)d_in[10];
    const float* pe_b2  = (const float*)d_in[11];
    const float* pn_w1  = (const float*)d_in[12];
    const float* pn_b1  = (const float*)d_in[13];
    const float* pn_w2  = (const float*)d_in[14];
    const float* pn_b2  = (const float*)d_in[15];
    const float* de_w1  = (const float*)d_in[16];
    const float* de_b1  = (const float*)d_in[17];
    const float* de_w2  = (const float*)d_in[18];
    const float* de_b2  = (const float*)d_in[19];
    const float* w_hr   = (const float*)d_in[20];
    const float* w_hi   = (const float*)d_in[21];
    const float* w_hn   = (const float*)d_in[22];
    const float* w_ir   = (const float*)d_in[23];
    const float* b_ir   = (const float*)d_in[24];
    const float* w_ii   = (const float*)d_in[25];
    const float* b_ii   = (const float*)d_in[26];
    const float* w_in   = (const float*)d_in[27];
    const float* b_in   = (const float*)d_in[28];

    float* out   = (float*)d_out;
    float* state = out + (size_t)TSTEPS * NROWS * NO;

    cudaFuncSetAttribute(fused_kernel,
                         cudaFuncAttributeMaxDynamicSharedMemorySize,
                         SMEM_BYTES);

    fused_kernel<<<GRID, 256, SMEM_BYTES>>>(
        enc_in, dec_in,
        enc_w1, enc_b1, enc_w2, enc_b2,
        pe_w1, pe_b1, pe_w2, pe_b2,
        pn_w1, pn_b1, pn_w2, pn_b2,
        de_w1, de_b1, de_w2, de_b2,
        w_hr, w_hi, w_hn,
        w_ir, b_ir, w_ii, b_ii, w_in, b_in,
        out, state);
}

// round 12
// speedup vs baseline: 1.4794x; 1.4794x over previous
#include <cuda_runtime.h>
#include <cuda_bf16.h>
#include <math.h>
#include <stdint.h>

// Problem constants
#define NROWS 512      // B*N = 16*32
#define NO 128         // node out dim
#define EH 256         // edge/node hidden dim
#define TSTEPS 25
#define GRID 128       // persistent CTAs (<= 148 SMs -> all resident)

// Scratch (device globals: no allocation allowed)
__device__ float g_x[NROWS * NO];        // node features / GRU hidden
__device__ float g_P[NROWS * EH];        // x @ W1_top
__device__ float g_Q[NROWS * EH];        // x @ W1_bot
__device__ float g_msg[NROWS * NO];      // edge2node mean message
__device__ uint32_t g_Whi[2][128 * 128]; // edge W2 bf16-hi, kpair packed [kp][128]
__device__ uint32_t g_Wlo[2][128 * 128];
__device__ uint32_t g_Wghi[128 * 512];   // GRU gate W [kp][512]: [Gr|Gi|Gn1|Gn2]
__device__ uint32_t g_Wglo[128 * 512];
__device__ uint32_t g_Wpqhi[2][64 * 512]; // P/Q W [kp][512]: [P|Q]; mat0=pe_w1, 1=de_w1
__device__ uint32_t g_Wpqlo[2][64 * 512];
__device__ float g_gates[NROWS * 512];    // gate GEMM output
__device__ uint32_t g_Ahi[NROWS * 64];    // packed activations (bf16x2 kpairs)
__device__ uint32_t g_Alo[NROWS * 64];

// ---------------------------------------------------------------------------
// Software grid barrier (all GRID CTAs resident).
// ---------------------------------------------------------------------------
__device__ unsigned g_bar_arrive = 0;
__device__ volatile unsigned g_bar_gen = 0;

__device__ __forceinline__ void grid_sync(unsigned &gen) {
    __threadfence();
    __syncthreads();
    if (threadIdx.x == 0) {
        unsigned old = atomicInc(&g_bar_arrive, GRID - 1);
        if (old == GRID - 1) {
            g_bar_gen = gen + 1;
        } else {
            while (g_bar_gen == gen) { }
        }
    }
    __syncthreads();
    gen++;
}

__device__ __forceinline__ void bf16split(float a0, float a1,
                                          uint32_t &hi, uint32_t &lo) {
    __nv_bfloat162 h2 = __floats2bfloat162_rn(a0, a1);
    float l0 = a0 - __low2float(h2);
    float l1 = a1 - __high2float(h2);
    __nv_bfloat162 l2 = __floats2bfloat162_rn(l0, l1);
    hi = *reinterpret_cast<uint32_t*>(&h2);
    lo = *reinterpret_cast<uint32_t*>(&l2);
}

__device__ __forceinline__ void mma_bf16(float (&d)[4], const uint32_t (&a)[4],
                                         uint32_t b0, uint32_t b1)
{
    asm volatile(
        "mma.sync.aligned.m16n8k16.row.col.f32.bf16.bf16.f32 "
        "{%0,%1,%2,%3}, {%4,%5,%6,%7}, {%8,%9}, {%0,%1,%2,%3};"
        : "+f"(d[0]), "+f"(d[1]), "+f"(d[2]), "+f"(d[3])
        : "r"(a[0]), "r"(a[1]), "r"(a[2]), "r"(a[3]), "r"(b0), "r"(b1));
}

// Shared memory: edge sA[2][128][132] | sB[2][32][136] | qb[4*256] | red[8*128]
#define SB_OFF (2*128*132)
#define SMEM_U32 (SB_OFF + 2*32*136 + 1024 + 1024)
#define SMEM_BYTES (SMEM_U32 * 4)

// ---------------------------------------------------------------------------
// Generic M=64 x N=128 x K=(64*KCHUNKS) bf16 hi/lo GEMM mainloop.
// A pre-built in smem (kpair u32, pitch PITCHA, lo at +64*PITCHA).
// B streamed from gmem [kp][ldB] at column offset ncol0.
// 8 warps: mtile = warp>>1 (16 rows), colhalf = warp&1 (64 cols).
// ---------------------------------------------------------------------------
template<int KCHUNKS, int PITCHA>
__device__ __forceinline__ void gemm64_mainloop(
    int tid, const uint32_t* __restrict__ Bhi, const uint32_t* __restrict__ Blo,
    int ldB, int ncol0, uint32_t* sA, uint32_t* sB, float (&d)[8][4])
{
    const int lane = tid & 31;
    const int warp = tid >> 5;
    const int g    = lane >> 2;
    const int tg   = lane & 3;
    const int mtile   = warp >> 1;
    const int colhalf = warp & 1;
    const int lrow = mtile * 16 + (lane & 7) + ((lane >> 3) & 1) * 8;
    const int lkof = ((lane >> 4) & 1) * 4;
    const uint32_t sA_base = (uint32_t)__cvta_generic_to_shared(sA);

#pragma unroll
    for (int j = 0; j < 8; j++)
#pragma unroll
        for (int r = 0; r < 4; r++) d[j][r] = 0.f;

    for (int ch = 0; ch < KCHUNKS; ch++) {
#pragma unroll
        for (int i = 0; i < 8; i++) {
            int lin = tid + i * 256;
            int split = lin >> 10;
            int rem = lin & 1023;
            int r = rem >> 5, c4 = rem & 31;
            const uint4* src = (const uint4*)((split ? Blo : Bhi)
                                              + (ch * 32 + r) * ldB + ncol0);
            *(uint4*)(sB + split * 4352 + r * 136 + c4 * 4) = src[c4];
        }
        __syncthreads();

#pragma unroll
        for (int t = 0; t < 4; t++) {
            const int kq = (ch * 4 + t) * 8;
            uint32_t ah[4], al[4];
            {
                uint32_t addr = sA_base + (uint32_t)(lrow * PITCHA + kq + lkof) * 4u;
                asm volatile("ldmatrix.sync.aligned.m8n8.x4.shared.b16 {%0,%1,%2,%3}, [%4];"
                    : "=r"(ah[0]), "=r"(ah[1]), "=r"(ah[2]), "=r"(ah[3]) : "r"(addr));
                addr += 64u * PITCHA * 4u;
                asm volatile("ldmatrix.sync.aligned.m8n8.x4.shared.b16 {%0,%1,%2,%3}, [%4];"
                    : "=r"(al[0]), "=r"(al[1]), "=r"(al[2]), "=r"(al[3]) : "r"(addr));
            }
            const int rb0 = (t * 8 + tg) * 136;
            const int rb1 = (t * 8 + 4 + tg) * 136;
#pragma unroll
            for (int j = 0; j < 8; j++) {
                int col = colhalf * 64 + j * 8 + g;
                uint32_t bh0 = sB[rb0 + col];
                uint32_t bh1 = sB[rb1 + col];
                uint32_t bl0 = sB[4352 + rb0 + col];
                uint32_t bl1 = sB[4352 + rb1 + col];
                mma_bf16(d[j], ah, bh0, bh1);
                mma_bf16(d[j], al, bh0, bh1);
                mma_bf16(d[j], ah, bl0, bl1);
            }
        }
        __syncthreads();
    }
}

// ---------------------------------------------------------------------------
// Edge phase (unchanged from R11): CTA = (b, 4 receivers), M=128 N=128 K=256.
// ---------------------------------------------------------------------------
__device__ void edge_phase(int cta, int tid, int mat,
                           const float* __restrict__ b1,
                           const float* __restrict__ b2, uint32_t* sm)
{
    uint32_t* sA = sm;
    uint32_t* sB = sm + SB_OFF;
    float*    qb = (float*)(sB + 2 * 32 * 136);
    float*    red = qb + 4 * 256;

    const int b   = cta >> 3;
    const int r0  = (cta & 7) * 4;
    const int bn0 = b * 32 + r0;

#pragma unroll
    for (int i = 0; i < 4; i++) {
        int idx = tid + i * 256;
        int r = idx >> 8, k = idx & 255;
        qb[idx] = g_Q[(bn0 + r) * EH + k] + b1[k];
    }
    __syncthreads();

#pragma unroll 4
    for (int i = 0; i < 64; i++) {
        int lin = tid + i * 256;
        int row = lin >> 7, kp = lin & 127;
        int recv = row >> 5, send = row & 31;
        float2 p = *(const float2*)(g_P + (b * 32 + send) * EH + 2 * kp);
        float2 q = *(const float2*)(qb + recv * 256 + 2 * kp);
        float a0 = fmaxf(p.x + q.x, 0.f);
        float a1 = fmaxf(p.y + q.y, 0.f);
        uint32_t hi, lo;
        bf16split(a0, a1, hi, lo);
        sA[row * 132 + kp]             = hi;
        sA[128 * 132 + row * 132 + kp] = lo;
    }
    __syncthreads();

    const int lane = tid & 31;
    const int warp = tid >> 5;
    const int g    = lane >> 2;
    const int tg   = lane & 3;
    const int lrow = warp * 16 + (lane & 7) + ((lane >> 3) & 1) * 8;
    const int lkof = ((lane >> 4) & 1) * 4;
    const uint32_t sA_base = (uint32_t)__cvta_generic_to_shared(sA);

    float d[16][4];
#pragma unroll
    for (int j = 0; j < 16; j++)
#pragma unroll
        for (int r = 0; r < 4; r++) d[j][r] = 0.f;

    const uint32_t* gWhi = g_Whi[mat];
    const uint32_t* gWlo = g_Wlo[mat];

    for (int ch = 0; ch < 4; ch++) {
#pragma unroll
        for (int i = 0; i < 8; i++) {
            int lin = tid + i * 256;
            int split = lin >> 10;
            int rem = lin & 1023;
            int r = rem >> 5, c4 = rem & 31;
            const uint4* src = (const uint4*)((split ? gWlo : gWhi) + ch * 32 * 128);
            *(uint4*)(sB + split * 4352 + r * 136 + c4 * 4) = src[r * 32 + c4];
        }
        __syncthreads();

#pragma unroll
        for (int t = 0; t < 4; t++) {
            const int kq = (ch * 4 + t) * 8;
            uint32_t ah[4], al[4];
            {
                uint32_t addr = sA_base + (uint32_t)(lrow * 132 + kq + lkof) * 4u;
                asm volatile("ldmatrix.sync.aligned.m8n8.x4.shared.b16 {%0,%1,%2,%3}, [%4];"
                    : "=r"(ah[0]), "=r"(ah[1]), "=r"(ah[2]), "=r"(ah[3]) : "r"(addr));
                addr += 128u * 132u * 4u;
                asm volatile("ldmatrix.sync.aligned.m8n8.x4.shared.b16 {%0,%1,%2,%3}, [%4];"
                    : "=r"(al[0]), "=r"(al[1]), "=r"(al[2]), "=r"(al[3]) : "r"(addr));
            }
            const int rb0 = (t * 8 + tg) * 136;
            const int rb1 = (t * 8 + 4 + tg) * 136;
#pragma unroll
            for (int j = 0; j < 16; j++) {
                int col = j * 8 + g;
                uint32_t bh0 = sB[rb0 + col];
                uint32_t bh1 = sB[rb1 + col];
                uint32_t bl0 = sB[4352 + rb0 + col];
                uint32_t bl1 = sB[4352 + rb1 + col];
                mma_bf16(d[j], ah, bh0, bh1);
                mma_bf16(d[j], al, bh0, bh1);
                mma_bf16(d[j], ah, bl0, bl1);
            }
        }
        __syncthreads();
    }

    const int recvL = warp >> 1;
    const int nrecv = r0 + recvL;
    const int sendA = (warp & 1) * 16 + g;
    const int sendB = sendA + 8;
    float t0[16], t1[16];
#pragma unroll
    for (int j = 0; j < 16; j++) {
        int c0 = j * 8 + 2 * tg;
        float bb0 = b2[c0], bb1 = b2[c0 + 1];
        float v00 = fmaxf(d[j][0] + bb0, 0.f);
        float v01 = fmaxf(d[j][1] + bb1, 0.f);
        float v10 = fmaxf(d[j][2] + bb0, 0.f);
        float v11 = fmaxf(d[j][3] + bb1, 0.f);
        if (sendA == nrecv) { v00 = 0.f; v01 = 0.f; }
        if (sendB == nrecv) { v10 = 0.f; v11 = 0.f; }
        t0[j] = v00 + v10;
        t1[j] = v01 + v11;
    }
#pragma unroll
    for (int off = 4; off < 32; off <<= 1) {
#pragma unroll
        for (int j = 0; j < 16; j++) {
            t0[j] += __shfl_xor_sync(0xffffffffu, t0[j], off);
            t1[j] += __shfl_xor_sync(0xffffffffu, t1[j], off);
        }
    }
    if (lane < 4) {
#pragma unroll
        for (int j = 0; j < 16; j++) {
            int c0 = j * 8 + 2 * lane;
            red[warp * 128 + c0]     = t0[j];
            red[warp * 128 + c0 + 1] = t1[j];
        }
    }
    __syncthreads();
#pragma unroll
    for (int i = 0; i < 2; i++) {
        int idx = tid + i * 256;
        int rv = idx >> 7, c = idx & 127;
        g_msg[(bn0 + rv) * 128 + c] =
            (red[(2 * rv) * 128 + c] + red[(2 * rv + 1) * 128 + c]) * (1.0f / 31.0f);
    }
}

// ---------------------------------------------------------------------------
// Gates phase: G[512,512] = [msg|h][512,256] @ Wg[256,512]. 32 CTAs.
// ---------------------------------------------------------------------------
__device__ void gates_phase(int cta, int tid, uint32_t* sm)
{
    if (cta >= 32) return;
    uint32_t* sA = sm;
    uint32_t* sB = sm + SB_OFF;
    const int m0 = (cta >> 2) * 64;
    const int ntile = cta & 3;

    // Build A: 64 rows x 128 kpairs; k<128 = msg, k>=128 = h
#pragma unroll 4
    for (int i = 0; i < 32; i++) {
        int lin = tid + i * 256;
        int row = lin >> 7, kp = lin & 127;
        int grow = m0 + row;
        float2 x = (kp < 64)
            ? *(const float2*)(g_msg + grow * 128 + 2 * kp)
            : *(const float2*)(g_x + grow * 128 + 2 * (kp - 64));
        uint32_t hi, lo;
        bf16split(x.x, x.y, hi, lo);
        sA[row * 132 + kp]            = hi;
        sA[64 * 132 + row * 132 + kp] = lo;
    }
    __syncthreads();

    float d[8][4];
    gemm64_mainloop<4, 132>(tid, g_Wghi, g_Wglo, 512, ntile * 128, sA, sB, d);

    const int lane = tid & 31, warp = tid >> 5;
    const int g = lane >> 2, tg = lane & 3;
    const int mtile = warp >> 1, colhalf = warp & 1;
#pragma unroll
    for (int j = 0; j < 8; j++) {
        int gcol = ntile * 128 + colhalf * 64 + j * 8 + 2 * tg;
        int rlo = m0 + mtile * 16 + g;
        *(float2*)(g_gates + rlo * 512 + gcol)       = make_float2(d[j][0], d[j][1]);
        *(float2*)(g_gates + (rlo + 8) * 512 + gcol) = make_float2(d[j][2], d[j][3]);
    }
}

// ---------------------------------------------------------------------------
// PQ phase: [P|Q][512,512] = Apk[512,128] @ Wpq[128,512]. 32 CTAs.
// ---------------------------------------------------------------------------
__device__ void pq_phase(int cta, int tid, int mat, uint32_t* sm)
{
    if (cta >= 32) return;
    uint32_t* sA = sm;
    uint32_t* sB = sm + SB_OFF;
    const int m0 = (cta >> 2) * 64;
    const int ntile = cta & 3;

    // Copy pre-packed A: 64 rows x 64 kpairs (hi + lo), uint4 vectorized
#pragma unroll
    for (int i = 0; i < 4; i++) {
        int lin = tid + i * 256;
        int row = lin >> 4, c4 = lin & 15;
        *(uint4*)(sA + row * 68 + c4 * 4) =
            ((const uint4*)(g_Ahi + (m0 + row) * 64))[c4];
        *(uint4*)(sA + 64 * 68 + row * 68 + c4 * 4) =
            ((const uint4*)(g_Alo + (m0 + row) * 64))[c4];
    }
    __syncthreads();

    float d[8][4];
    gemm64_mainloop<2, 68>(tid, g_Wpqhi[mat], g_Wpqlo[mat], 512, ntile * 128, sA, sB, d);

    const int lane = tid & 31, warp = tid >> 5;
    const int g = lane >> 2, tg = lane & 3;
    const int mtile = warp >> 1, colhalf = warp & 1;
    float* dst = (ntile < 2) ? g_P : g_Q;
    int cbase = (ntile & 1) * 128 + colhalf * 64;
#pragma unroll
    for (int j = 0; j < 8; j++) {
        int gcol = cbase + j * 8 + 2 * tg;
        int rlo = m0 + mtile * 16 + g;
        *(float2*)(dst + rlo * 256 + gcol)       = make_float2(d[j][0], d[j][1]);
        *(float2*)(dst + (rlo + 8) * 256 + gcol) = make_float2(d[j][2], d[j][3]);
    }
}

// ---------------------------------------------------------------------------
// Elementwise GRU update + h' packing. All 128 CTAs (1 col-pair per thread).
// ---------------------------------------------------------------------------
__device__ void elem_phase(int cta, int tid, const float* __restrict__ dec_t,
    const float* __restrict__ w_ir, const float* __restrict__ b_ir,
    const float* __restrict__ w_ii, const float* __restrict__ b_ii,
    const float* __restrict__ w_in, const float* __restrict__ b_in,
    float* __restrict__ out_t, float* __restrict__ state)
{
    int idx = cta * 256 + tid;       // 0..32767
    int row = idx >> 6, cp = idx & 63;
    int c0 = 2 * cp;

    float2 Gr  = *(const float2*)(g_gates + row * 512 + c0);
    float2 Gi  = *(const float2*)(g_gates + row * 512 + 128 + c0);
    float2 Gn1 = *(const float2*)(g_gates + row * 512 + 256 + c0);
    float2 Gn2 = *(const float2*)(g_gates + row * 512 + 384 + c0);
    float2 h   = *(const float2*)(g_x + row * 128 + c0);
    float2 br  = *(const float2*)(b_ir + c0);
    float2 bi  = *(const float2*)(b_ii + c0);
    float2 bn  = *(const float2*)(b_in + c0);

    float d0 = dec_t[row * 3 + 0], d1 = dec_t[row * 3 + 1], d2 = dec_t[row * 3 + 2];
    float2 rsum = make_float2(0.f, 0.f), isum = make_float2(0.f, 0.f), nsum = make_float2(0.f, 0.f);
#pragma unroll
    for (int jj = 0; jj < 3; jj++) {
        float dv = (jj == 0) ? d0 : (jj == 1) ? d1 : d2;
        float2 wr = *(const float2*)(w_ir + (128 + jj) * 128 + c0);
        float2 wi = *(const float2*)(w_ii + (128 + jj) * 128 + c0);
        float2 wn = *(const float2*)(w_in + (128 + jj) * 128 + c0);
        rsum.x = fmaf(dv, wr.x, rsum.x); rsum.y = fmaf(dv, wr.y, rsum.y);
        isum.x = fmaf(dv, wi.x, isum.x); isum.y = fmaf(dv, wi.y, isum.y);
        nsum.x = fmaf(dv, wn.x, nsum.x); nsum.y = fmaf(dv, wn.y, nsum.y);
    }

    float rr0 = 1.f / (1.f + expf(-(Gr.x + rsum.x + br.x)));
    float rr1 = 1.f / (1.f + expf(-(Gr.y + rsum.y + br.y)));
    float ii0 = 1.f / (1.f + expf(-(Gi.x + isum.x + bi.x)));
    float ii1 = 1.f / (1.f + expf(-(Gi.y + isum.y + bi.y)));
    float nn0 = tanhf(Gn1.x + nsum.x + bn.x + rr0 * Gn2.x);
    float nn1 = tanhf(Gn1.y + nsum.y + bn.y + rr1 * Gn2.y);
    float hv0 = (1.f - ii0) * nn0 + ii0 * h.x;
    float hv1 = (1.f - ii1) * nn1 + ii1 * h.y;

    *(float2*)(g_x + row * 128 + c0)   = make_float2(hv0, hv1);
    *(float2*)(out_t + row * 128 + c0) = make_float2(hv0, hv1);
    if (state) *(float2*)(state + row * 128 + c0) = make_float2(hv0, hv1);

    uint32_t hi, lo;
    bf16split(hv0, hv1, hi, lo);
    g_Ahi[row * 64 + cp] = hi;
    g_Alo[row * 64 + cp] = lo;
}

// ---------------------------------------------------------------------------
// MLP phase (coalesced layers) + pack x into g_Ahi/g_Alo. 128 CTAs x 4 rows.
// ---------------------------------------------------------------------------
template<int K1>
__device__ void mlp_phase(int cta, int tid, const float* __restrict__ in,
                          const float* __restrict__ w1, const float* __restrict__ b1,
                          const float* __restrict__ w2, const float* __restrict__ b2,
                          uint32_t* sm)
{
    float* in_s = (float*)sm;          // [4][K1]
    float* hid  = in_s + 4 * K1;       // [4][256]
    float* xs   = hid + 4 * 256;       // [4][128]

    const int row0 = cta * 4;
    for (int idx = tid; idx < 4 * K1; idx += 256)
        in_s[idx] = in[row0 * K1 + idx];
    __syncthreads();

    {
        const int j = tid;
        float acc[4] = {0.f, 0.f, 0.f, 0.f};
#pragma unroll 8
        for (int k = 0; k < K1; k++) {
            float w = w1[k * EH + j];
#pragma unroll
            for (int r = 0; r < 4; r++) acc[r] = fmaf(in_s[r * K1 + k], w, acc[r]);
        }
        float bb = b1[j];
#pragma unroll
        for (int r = 0; r < 4; r++) hid[r * 256 + j] = fmaxf(acc[r] + bb, 0.f);
    }
    __syncthreads();

    {
        const int c = tid & 127, g2 = tid >> 7;
        float acc[2] = {0.f, 0.f};
#pragma unroll 8
        for (int k = 0; k < EH; k++) {
            float w = w2[k * NO + c];
#pragma unroll
            for (int r = 0; r < 2; r++) acc[r] = fmaf(hid[(g2 * 2 + r) * 256 + k], w, acc[r]);
        }
        float bb = b2[c];
#pragma unroll
        for (int r = 0; r < 2; r++) {
            float o = fmaxf(acc[r] + bb, 0.f);
            xs[(g2 * 2 + r) * 128 + c] = o;
            g_x[(row0 + g2 * 2 + r) * NO + c] = o;
        }
    }
    __syncthreads();

    // pack xs -> g_Ahi/g_Alo
    {
        int r = tid >> 6, cp = tid & 63;
        float2 x = *(const float2*)(xs + r * 128 + 2 * cp);
        uint32_t hi, lo;
        bf16split(x.x, x.y, hi, lo);
        g_Ahi[(row0 + r) * 64 + cp] = hi;
        g_Alo[(row0 + r) * 64 + cp] = lo;
    }
}

// ---------------------------------------------------------------------------
// Single persistent kernel.
// ---------------------------------------------------------------------------
__global__ __launch_bounds__(256, 1) void fused_kernel(
    const float* __restrict__ enc_in, const float* __restrict__ dec_in,
    const float* __restrict__ enc_w1, const float* __restrict__ enc_b1,
    const float* __restrict__ enc_w2, const float* __restrict__ enc_b2,
    const float* __restrict__ pe_w1,  const float* __restrict__ pe_b1,
    const float* __restrict__ pe_w2,  const float* __restrict__ pe_b2,
    const float* __restrict__ pn_w1,  const float* __restrict__ pn_b1,
    const float* __restrict__ pn_w2,  const float* __restrict__ pn_b2,
    const float* __restrict__ de_w1,  const float* __restrict__ de_b1,
    const float* __restrict__ de_w2,  const float* __restrict__ de_b2,
    const float* __restrict__ w_hr, const float* __restrict__ w_hi,
    const float* __restrict__ w_hn,
    const float* __restrict__ w_ir, const float* __restrict__ b_ir,
    const float* __restrict__ w_ii, const float* __restrict__ b_ii,
    const float* __restrict__ w_in, const float* __restrict__ b_in,
    float* __restrict__ out, float* __restrict__ state)
{
    extern __shared__ uint32_t sm[];
    const int cta = blockIdx.x;
    const int tid = threadIdx.x;
    unsigned gen = g_bar_gen;

    // ---- phase 0: weight packing ----
    {
        int gid = cta * 256 + tid;   // 0..32767
        // edge W2 hi/lo (2 x 16384 items)
        {
            int mat = gid >> 14, rem = gid & 16383;
            int r = rem >> 7, n = rem & 127;
            const float* W = mat ? de_w2 : pe_w2;
            uint32_t hi, lo;
            bf16split(W[(2 * r) * 128 + n], W[(2 * r + 1) * 128 + n], hi, lo);
            g_Whi[mat][r * 128 + n] = hi;
            g_Wlo[mat][r * 128 + n] = lo;
        }
        // Wg [128 kp][512]: blocks [Gr|Gi|Gn1|Gn2] (65536 items)
#pragma unroll
        for (int i = 0; i < 2; i++) {
            int t = gid + i * 32768;
            int kp = t >> 9, n = t & 511;
            int blk = n >> 7, nn = n & 127;
            float v0, v1;
            int k0 = 2 * kp, k1 = 2 * kp + 1;
            const float* Wm; const float* Wh;
            if (blk == 0) { Wm = w_ir; Wh = w_hr; }
            else if (blk == 1) { Wm = w_ii; Wh = w_hi; }
            else if (blk == 2) { Wm = w_in; Wh = nullptr; }
            else { Wm = nullptr; Wh = w_hn; }
            v0 = (k0 < 128) ? (Wm ? Wm[k0 * 128 + nn] : 0.f)
                            : (Wh ? Wh[(k0 - 128) * 128 + nn] : 0.f);
            v1 = (k1 < 128) ? (Wm ? Wm[k1 * 128 + nn] : 0.f)
                            : (Wh ? Wh[(k1 - 128) * 128 + nn] : 0.f);
            uint32_t hi, lo;
            bf16split(v0, v1, hi, lo);
            g_Wghi[kp * 512 + n] = hi;
            g_Wglo[kp * 512 + n] = lo;
        }
        // Wpq [2 mats][64 kp][512]: [P|Q] (65536 items)
#pragma unroll
        for (int i = 0; i < 2; i++) {
            int t = gid + i * 32768;
            int mat = t >> 15, rem = t & 32767;
            int kp = rem >> 9, n = rem & 511;
            const float* W1 = mat ? de_w1 : pe_w1;
            int k0 = 2 * kp, k1 = 2 * kp + 1;
            float v0 = (n < 256) ? W1[k0 * 256 + n] : W1[(128 + k0) * 256 + (n - 256)];
            float v1 = (n < 256) ? W1[k1 * 256 + n] : W1[(128 + k1) * 256 + (n - 256)];
            uint32_t hi, lo;
            bf16split(v0, v1, hi, lo);
            g_Wpqhi[mat][kp * 512 + n] = hi;
            g_Wpqlo[mat][kp * 512 + n] = lo;
        }
    }
    grid_sync(gen);

    // ---- encoder mlp1, then P/Q (pe) ----
    mlp_phase<150>(cta, tid, enc_in, enc_w1, enc_b1, enc_w2, enc_b2, sm);
    grid_sync(gen);
    pq_phase(cta, tid, 0, sm);
    grid_sync(gen);

    // ---- two message-passing rounds ----
    for (int p = 0; p < 2; p++) {
        edge_phase(cta, tid, 0, pe_b1, pe_b2, sm);
        grid_sync(gen);
        mlp_phase<128>(cta, tid, g_msg, pn_w1, pn_b1, pn_w2, pn_b2, sm);
        grid_sync(gen);
        pq_phase(cta, tid, (p == 0) ? 0 : 1, sm);
        grid_sync(gen);
    }

    // ---- decoder: 25 GRU steps ----
    for (int t = 0; t < TSTEPS; t++) {
        edge_phase(cta, tid, 1, de_b1, de_b2, sm);
        grid_sync(gen);
        gates_phase(cta, tid, sm);
        grid_sync(gen);
        elem_phase(cta, tid, dec_in + (size_t)t * NROWS * 3,
                   w_ir, b_ir, w_ii, b_ii, w_in, b_in,
                   out + (size_t)t * NROWS * NO,
                   (t == TSTEPS - 1) ? state : nullptr);
        grid_sync(gen);
        if (t != TSTEPS - 1) pq_phase(cta, tid, 1, sm);
        grid_sync(gen);
    }
}

// ---------------------------------------------------------------------------
extern "C" void kernel_launch(void* const* d_in, const int* in_sizes, int n_in,
                              void* d_out, int out_size)
{
    const float* enc_in = (const float*)d_in[0];
    const float* dec_in = (const float*)d_in[1];
    const float* enc_w1 = (const float*)d_in[4];
    const float* enc_b1 = (const float*)d_in[5];
    const float* enc_w2 = (const float*)d_in[6];
    const float* enc_b2 = (const float*)d_in[7];
    const float* pe_w1  = (const float*)d_in[8];
    const float* pe_b1  = (const float*)d_in[9];
    const float* pe_w2  = (const float*)d_in[10];
    const float* pe_b2  = (const float*)d_in[11];
    const float* pn_w1  = (const float*)d_in[12];
    const float* pn_b1  = (const float*)d_in[13];
    const float* pn_w2  = (const float*)d_in[14];
    const float* pn_b2  = (const float*)d_in[15];
    const float* de_w1  = (const float*)d_in[16];
    const float* de_b1  = (const float*)d_in[17];
    const float* de_w2  = (const float*)d_in[18];
    const float* de_b2  = (const float*)d_in[19];
    const float* w_hr   = (const float*)d_in[20];
    const float* w_hi   = (const float*)d_in[21];
    const float* w_hn   = (const float*)d_in[22];
    const float* w_ir   = (const float*)d_in[23];
    const float* b_ir   = (const float*)d_in[24];
    const float* w_ii   = (const float*)d_in[25];
    const float* b_ii   = (const float*)d_in[26];
    const float* w_in   = (const float*)d_in[27];
    const float* b_in   = (const float*)d_in[28];

    float* out   = (float*)d_out;
    float* state = out + (size_t)TSTEPS * NROWS * NO;

    cudaFuncSetAttribute(fused_kernel,
                         cudaFuncAttributeMaxDynamicSharedMemorySize,
                         SMEM_BYTES);

    fused_kernel<<<GRID, 256, SMEM_BYTES>>>(
        enc_in, dec_in,
        enc_w1, enc_b1, enc_w2, enc_b2,
        pe_w1, pe_b1, pe_w2, pe_b2,
        pn_w1, pn_b1, pn_w2, pn_b2,
        de_w1, de_b1, de_w2, de_b2,
        w_hr, w_hi, w_hn,
        w_ir, b_ir, w_ii, b_ii, w_in, b_in,
        out, state);
}

// round 13
// speedup vs baseline: 1.9817x; 1.3395x over previous
#include <cuda_runtime.h>
#include <cuda_bf16.h>
#include <math.h>
#include <stdint.h>

// Problem constants
#define NROWS 512      // B*N = 16*32
#define NO 128         // node out dim
#define EH 256         // edge/node hidden dim
#define TSTEPS 25
#define GRID 128       // persistent CTAs (<= 148 SMs -> all resident)
#define NGRP 16        // one group of 8 CTAs per batch element

// Scratch (device globals: no allocation allowed)
__device__ float g_x[NROWS * NO];        // node features / GRU hidden
__device__ float g_P[NROWS * EH];        // x @ W1_top
__device__ float g_Q[NROWS * EH];        // x @ W1_bot
__device__ float g_msg[NROWS * NO];      // edge2node mean message
__device__ uint32_t g_Whi[2][128 * 128]; // edge W2 bf16-hi, kpair packed [kp][128]
__device__ uint32_t g_Wlo[2][128 * 128];
__device__ uint32_t g_Wghi[128 * 512];   // GRU gate W [kp][512]: [Gr|Gi|Gn1|Gn2]
__device__ uint32_t g_Wglo[128 * 512];
__device__ uint32_t g_Wpqhi[2][64 * 512]; // P/Q W [kp][512]: [P|Q]; mat0=pe_w1, 1=de_w1
__device__ uint32_t g_Wpqlo[2][64 * 512];
__device__ float g_gates[NROWS * 512];    // gate GEMM output
__device__ uint32_t g_Ahi[NROWS * 64];    // packed activations (bf16x2 kpairs)
__device__ uint32_t g_Alo[NROWS * 64];

// ---------------------------------------------------------------------------
// Barriers. One grid barrier (after packing), then per-group (8 CTA) barriers.
// __threadfence() flushes L1D on sm_103a -> post-barrier loads are coherent.
// ---------------------------------------------------------------------------
__device__ unsigned g_bar_arrive = 0;
__device__ volatile unsigned g_bar_gen = 0;
__device__ unsigned g_grp_arrive[NGRP];
__device__ volatile unsigned g_grp_gen[NGRP];

__device__ __forceinline__ void grid_sync(unsigned &gen) {
    __threadfence();
    __syncthreads();
    if (threadIdx.x == 0) {
        unsigned old = atomicInc(&g_bar_arrive, GRID - 1);
        if (old == GRID - 1) g_bar_gen = gen + 1;
        else while (g_bar_gen == gen) { }
    }
    __syncthreads();
    gen++;
}

__device__ __forceinline__ void group_sync(int grp, unsigned &gen) {
    __threadfence();
    __syncthreads();
    if (threadIdx.x == 0) {
        unsigned old = atomicInc(&g_grp_arrive[grp], 7);
        if (old == 7) g_grp_gen[grp] = gen + 1;
        else while (g_grp_gen[grp] == gen) { }
    }
    __syncthreads();
    gen++;
}

// cp.async helpers
#define CP_ASYNC16(dst, src) \
    asm volatile("cp.async.cg.shared.global [%0], [%1], 16;" :: "r"(dst), "l"(src))
#define CP_COMMIT() asm volatile("cp.async.commit_group;")
#define CP_WAIT1()  asm volatile("cp.async.wait_group 1;")
#define CP_WAIT0()  asm volatile("cp.async.wait_group 0;")

__device__ __forceinline__ void bf16split(float a0, float a1,
                                          uint32_t &hi, uint32_t &lo) {
    __nv_bfloat162 h2 = __floats2bfloat162_rn(a0, a1);
    float l0 = a0 - __low2float(h2);
    float l1 = a1 - __high2float(h2);
    __nv_bfloat162 l2 = __floats2bfloat162_rn(l0, l1);
    hi = *reinterpret_cast<uint32_t*>(&h2);
    lo = *reinterpret_cast<uint32_t*>(&l2);
}

__device__ __forceinline__ void mma_bf16(float (&d)[4], const uint32_t (&a)[4],
                                         uint32_t b0, uint32_t b1)
{
    asm volatile(
        "mma.sync.aligned.m16n8k16.row.col.f32.bf16.bf16.f32 "
        "{%0,%1,%2,%3}, {%4,%5,%6,%7}, {%8,%9}, {%0,%1,%2,%3};"
        : "+f"(d[0]), "+f"(d[1]), "+f"(d[2]), "+f"(d[3])
        : "r"(a[0]), "r"(a[1]), "r"(a[2]), "r"(a[3]), "r"(b0), "r"(b1));
}

// Shared memory (u32): edge sA [2][128][132] | sB double-buf 2x8704 | qb 1024 | red 1024
#define SB_OFF (2*128*132)
#define SMEM_U32 (SB_OFF + 2*8704 + 1024 + 1024)
#define SMEM_BYTES (SMEM_U32 * 4)

// ---------------------------------------------------------------------------
// Edge phase: CTA = (b, 4 receivers). M=128 (4 recv x 32 send), N=128, K=256.
// bf16 hi/lo 3-MMA. B double-buffered via cp.async.
// ---------------------------------------------------------------------------
__device__ void edge_phase(int cta, int tid, int mat,
                           const float* __restrict__ b1,
                           const float* __restrict__ b2, uint32_t* sm)
{
    uint32_t* sA = sm;                     // hi [128][132], lo at +128*132
    uint32_t* sB = sm + SB_OFF;            // 2 bufs x (hi[32][136] + lo[32][136])
    float*    qb = (float*)(sB + 2 * 8704);
    float*    red = qb + 1024;

    const int b   = cta >> 3;
    const int r0  = (cta & 7) * 4;
    const int bn0 = b * 32 + r0;

    const uint32_t* gWhi = g_Whi[mat];
    const uint32_t* gWlo = g_Wlo[mat];
    const uint32_t sB_base = (uint32_t)__cvta_generic_to_shared(sB);

    auto stage = [&](int ch, int buf) {
#pragma unroll
        for (int i = 0; i < 8; i++) {
            int lin = tid + i * 256;
            int split = lin >> 10;
            int rem = lin & 1023;
            int r = rem >> 5, c4 = rem & 31;
            const uint32_t* src = (split ? gWlo : gWhi) + ch * 32 * 128 + r * 128 + c4 * 4;
            uint32_t dst = sB_base + (uint32_t)(buf * 8704 + split * 4352 + r * 136 + c4 * 4) * 4u;
            CP_ASYNC16(dst, src);
        }
        CP_COMMIT();
    };

    stage(0, 0);   // overlap chunk-0 load with qb/A build

#pragma unroll
    for (int i = 0; i < 4; i++) {
        int idx = tid + i * 256;
        int r = idx >> 8, k = idx & 255;
        qb[idx] = g_Q[(bn0 + r) * EH + k] + b1[k];
    }
    __syncthreads();

#pragma unroll 4
    for (int i = 0; i < 64; i++) {
        int lin = tid + i * 256;
        int row = lin >> 7, kp = lin & 127;
        int recv = row >> 5, send = row & 31;
        float2 p = *(const float2*)(g_P + (b * 32 + send) * EH + 2 * kp);
        float2 q = *(const float2*)(qb + recv * 256 + 2 * kp);
        float a0 = fmaxf(p.x + q.x, 0.f);
        float a1 = fmaxf(p.y + q.y, 0.f);
        uint32_t hi, lo;
        bf16split(a0, a1, hi, lo);
        sA[row * 132 + kp]             = hi;
        sA[128 * 132 + row * 132 + kp] = lo;
    }

    const int lane = tid & 31;
    const int warp = tid >> 5;
    const int g    = lane >> 2;
    const int tg   = lane & 3;
    const int lrow = warp * 16 + (lane & 7) + ((lane >> 3) & 1) * 8;
    const int lkof = ((lane >> 4) & 1) * 4;
    const uint32_t sA_base = (uint32_t)__cvta_generic_to_shared(sA);

    float d[16][4];
#pragma unroll
    for (int j = 0; j < 16; j++)
#pragma unroll
        for (int r = 0; r < 4; r++) d[j][r] = 0.f;

    for (int ch = 0; ch < 4; ch++) {
        if (ch < 3) { stage(ch + 1, (ch + 1) & 1); CP_WAIT1(); }
        else        { CP_WAIT0(); }
        __syncthreads();
        uint32_t* sBuf = sB + (ch & 1) * 8704;

#pragma unroll
        for (int t = 0; t < 4; t++) {
            const int kq = (ch * 4 + t) * 8;
            uint32_t ah[4], al[4];
            {
                uint32_t addr = sA_base + (uint32_t)(lrow * 132 + kq + lkof) * 4u;
                asm volatile("ldmatrix.sync.aligned.m8n8.x4.shared.b16 {%0,%1,%2,%3}, [%4];"
                    : "=r"(ah[0]), "=r"(ah[1]), "=r"(ah[2]), "=r"(ah[3]) : "r"(addr));
                addr += 128u * 132u * 4u;
                asm volatile("ldmatrix.sync.aligned.m8n8.x4.shared.b16 {%0,%1,%2,%3}, [%4];"
                    : "=r"(al[0]), "=r"(al[1]), "=r"(al[2]), "=r"(al[3]) : "r"(addr));
            }
            const int rb0 = (t * 8 + tg) * 136;
            const int rb1 = (t * 8 + 4 + tg) * 136;
#pragma unroll
            for (int j = 0; j < 16; j++) {
                int col = j * 8 + g;
                uint32_t bh0 = sBuf[rb0 + col];
                uint32_t bh1 = sBuf[rb1 + col];
                uint32_t bl0 = sBuf[4352 + rb0 + col];
                uint32_t bl1 = sBuf[4352 + rb1 + col];
                mma_bf16(d[j], ah, bh0, bh1);
                mma_bf16(d[j], al, bh0, bh1);
                mma_bf16(d[j], ah, bl0, bl1);
            }
        }
        __syncthreads();
    }

    // Epilogue: bias + ReLU + self-edge exclusion + sender-sum (mean over 31)
    const int recvL = warp >> 1;
    const int nrecv = r0 + recvL;
    const int sendA = (warp & 1) * 16 + g;
    const int sendB = sendA + 8;
    float t0[16], t1[16];
#pragma unroll
    for (int j = 0; j < 16; j++) {
        int c0 = j * 8 + 2 * tg;
        float bb0 = b2[c0], bb1 = b2[c0 + 1];
        float v00 = fmaxf(d[j][0] + bb0, 0.f);
        float v01 = fmaxf(d[j][1] + bb1, 0.f);
        float v10 = fmaxf(d[j][2] + bb0, 0.f);
        float v11 = fmaxf(d[j][3] + bb1, 0.f);
        if (sendA == nrecv) { v00 = 0.f; v01 = 0.f; }
        if (sendB == nrecv) { v10 = 0.f; v11 = 0.f; }
        t0[j] = v00 + v10;
        t1[j] = v01 + v11;
    }
#pragma unroll
    for (int off = 4; off < 32; off <<= 1) {
#pragma unroll
        for (int j = 0; j < 16; j++) {
            t0[j] += __shfl_xor_sync(0xffffffffu, t0[j], off);
            t1[j] += __shfl_xor_sync(0xffffffffu, t1[j], off);
        }
    }
    if (lane < 4) {
#pragma unroll
        for (int j = 0; j < 16; j++) {
            int c0 = j * 8 + 2 * lane;
            red[warp * 128 + c0]     = t0[j];
            red[warp * 128 + c0 + 1] = t1[j];
        }
    }
    __syncthreads();
#pragma unroll
    for (int i = 0; i < 2; i++) {
        int idx = tid + i * 256;
        int rv = idx >> 7, c = idx & 127;
        g_msg[(bn0 + rv) * 128 + c] =
            (red[(2 * rv) * 128 + c] + red[(2 * rv + 1) * 128 + c]) * (1.0f / 31.0f);
    }
}

// ---------------------------------------------------------------------------
// M=32 x N=64 x K=(64*KCHUNKS) bf16 hi/lo GEMM mainloop (group phases).
// A in smem (kpair u32, pitch PITCHA, lo at +32*PITCHA). B from gmem [kp][512]
// at column ncol0, cp.async double-buffered (bufs of 4608 u32, pitch 72).
// 8 warps: mtile = warp>>2 (16 rows), ncolq = warp&3 (16 cols).
// ---------------------------------------------------------------------------
template<int KCHUNKS, int PITCHA>
__device__ __forceinline__ void gemm32_mainloop(
    int tid, const uint32_t* __restrict__ Bhi, const uint32_t* __restrict__ Blo,
    int ncol0, uint32_t* sA, uint32_t* sB, float (&d)[2][4])
{
    const int lane = tid & 31;
    const int warp = tid >> 5;
    const int g    = lane >> 2;
    const int tg   = lane & 3;
    const int ncolq = warp & 3;
    const int mtile = warp >> 2;
    const int lrow = mtile * 16 + (lane & 7) + ((lane >> 3) & 1) * 8;
    const int lkof = ((lane >> 4) & 1) * 4;
    const uint32_t sA_base = (uint32_t)__cvta_generic_to_shared(sA);
    const uint32_t sB_base = (uint32_t)__cvta_generic_to_shared(sB);

#pragma unroll
    for (int j = 0; j < 2; j++)
#pragma unroll
        for (int r = 0; r < 4; r++) d[j][r] = 0.f;

    auto stage = [&](int ch, int buf) {
#pragma unroll
        for (int i = 0; i < 4; i++) {
            int lin = tid + i * 256;
            int split = lin >> 9;
            int rem = lin & 511;
            int r = rem >> 4, c4 = rem & 15;
            const uint32_t* src = (split ? Blo : Bhi) + (ch * 32 + r) * 512 + ncol0 + c4 * 4;
            uint32_t dst = sB_base + (uint32_t)(buf * 4608 + split * 2304 + r * 72 + c4 * 4) * 4u;
            CP_ASYNC16(dst, src);
        }
        CP_COMMIT();
    };

    stage(0, 0);
    for (int ch = 0; ch < KCHUNKS; ch++) {
        if (ch + 1 < KCHUNKS) { stage(ch + 1, (ch + 1) & 1); CP_WAIT1(); }
        else                  { CP_WAIT0(); }
        __syncthreads();
        uint32_t* sBuf = sB + (ch & 1) * 4608;
#pragma unroll
        for (int t = 0; t < 4; t++) {
            const int kq = (ch * 4 + t) * 8;
            uint32_t ah[4], al[4];
            {
                uint32_t addr = sA_base + (uint32_t)(lrow * PITCHA + kq + lkof) * 4u;
                asm volatile("ldmatrix.sync.aligned.m8n8.x4.shared.b16 {%0,%1,%2,%3}, [%4];"
                    : "=r"(ah[0]), "=r"(ah[1]), "=r"(ah[2]), "=r"(ah[3]) : "r"(addr));
                addr += 32u * PITCHA * 4u;
                asm volatile("ldmatrix.sync.aligned.m8n8.x4.shared.b16 {%0,%1,%2,%3}, [%4];"
                    : "=r"(al[0]), "=r"(al[1]), "=r"(al[2]), "=r"(al[3]) : "r"(addr));
            }
            const int rb0 = (t * 8 + tg) * 72;
            const int rb1 = (t * 8 + 4 + tg) * 72;
#pragma unroll
            for (int j = 0; j < 2; j++) {
                int col = ncolq * 16 + j * 8 + g;
                uint32_t bh0 = sBuf[rb0 + col];
                uint32_t bh1 = sBuf[rb1 + col];
                uint32_t bl0 = sBuf[2304 + rb0 + col];
                uint32_t bl1 = sBuf[2304 + rb1 + col];
                mma_bf16(d[j], ah, bh0, bh1);
                mma_bf16(d[j], al, bh0, bh1);
                mma_bf16(d[j], ah, bl0, bl1);
            }
        }
        __syncthreads();
    }
}

// ---------------------------------------------------------------------------
// Gates phase (group): G[b rows, 512] = [msg|h][32,256] @ Wg[256,512].
// CTA gcta computes cols gcta*64..+63.
// ---------------------------------------------------------------------------
__device__ void gates_phase_g(int b, int gcta, int tid, uint32_t* sm)
{
    uint32_t* sA = sm;
    uint32_t* sB = sm + SB_OFF;
    const int m0 = b * 32;

#pragma unroll
    for (int i = 0; i < 16; i++) {
        int lin = tid + i * 256;
        int row = lin >> 7, kp = lin & 127;
        int grow = m0 + row;
        float2 x = (kp < 64)
            ? *(const float2*)(g_msg + grow * 128 + 2 * kp)
            : *(const float2*)(g_x + grow * 128 + 2 * (kp - 64));
        uint32_t hi, lo;
        bf16split(x.x, x.y, hi, lo);
        sA[row * 132 + kp]            = hi;
        sA[32 * 132 + row * 132 + kp] = lo;
    }

    float d[2][4];
    gemm32_mainloop<4, 132>(tid, g_Wghi, g_Wglo, gcta * 64, sA, sB, d);

    const int lane = tid & 31, warp = tid >> 5;
    const int g = lane >> 2, tg = lane & 3;
    const int mtile = warp >> 2, ncolq = warp & 3;
#pragma unroll
    for (int j = 0; j < 2; j++) {
        int gcol = gcta * 64 + ncolq * 16 + j * 8 + 2 * tg;
        int rlo = m0 + mtile * 16 + g;
        *(float2*)(g_gates + rlo * 512 + gcol)       = make_float2(d[j][0], d[j][1]);
        *(float2*)(g_gates + (rlo + 8) * 512 + gcol) = make_float2(d[j][2], d[j][3]);
    }
}

// ---------------------------------------------------------------------------
// PQ phase (group): [P|Q][32,512] = Apk[32,128] @ Wpq[128,512].
// ---------------------------------------------------------------------------
__device__ void pq_phase_g(int b, int gcta, int tid, int mat, uint32_t* sm)
{
    uint32_t* sA = sm;
    uint32_t* sB = sm + SB_OFF;
    const int m0 = b * 32;

#pragma unroll
    for (int i = 0; i < 4; i++) {
        int lin = tid + i * 256;          // 0..1023
        int split = lin >> 9;
        int rem = lin & 511;
        int row = rem >> 4, c4 = rem & 15;
        uint4 v = ((const uint4*)((split ? g_Alo : g_Ahi) + (m0 + row) * 64))[c4];
        *(uint4*)(sA + split * 32 * 68 + row * 68 + c4 * 4) = v;
    }

    float d[2][4];
    gemm32_mainloop<2, 68>(tid, g_Wpqhi[mat], g_Wpqlo[mat], gcta * 64, sA, sB, d);

    const int lane = tid & 31, warp = tid >> 5;
    const int g = lane >> 2, tg = lane & 3;
    const int mtile = warp >> 2, ncolq = warp & 3;
    const int gncol0 = gcta * 64 + ncolq * 16;
    float* dst = (gncol0 < 256) ? g_P : g_Q;
    const int cbase = (gncol0 < 256) ? gncol0 : gncol0 - 256;
#pragma unroll
    for (int j = 0; j < 2; j++) {
        int gcol = cbase + j * 8 + 2 * tg;
        int rlo = m0 + mtile * 16 + g;
        *(float2*)(dst + rlo * 256 + gcol)       = make_float2(d[j][0], d[j][1]);
        *(float2*)(dst + (rlo + 8) * 256 + gcol) = make_float2(d[j][2], d[j][3]);
    }
}

// ---------------------------------------------------------------------------
// Elementwise GRU update + h' packing (group: 8 CTAs x 256 thr = 2048 items).
// ---------------------------------------------------------------------------
__device__ void elem_phase_g(int b, int gcta, int tid, const float* __restrict__ dec_t,
    const float* __restrict__ w_ir, const float* __restrict__ b_ir,
    const float* __restrict__ w_ii, const float* __restrict__ b_ii,
    const float* __restrict__ w_in, const float* __restrict__ b_in,
    float* __restrict__ out_t, float* __restrict__ state)
{
    int idx = gcta * 256 + tid;       // 0..2047
    int row = b * 32 + (idx >> 6);
    int cp = idx & 63;
    int c0 = 2 * cp;

    float2 Gr  = *(const float2*)(g_gates + row * 512 + c0);
    float2 Gi  = *(const float2*)(g_gates + row * 512 + 128 + c0);
    float2 Gn1 = *(const float2*)(g_gates + row * 512 + 256 + c0);
    float2 Gn2 = *(const float2*)(g_gates + row * 512 + 384 + c0);
    float2 h   = *(const float2*)(g_x + row * 128 + c0);
    float2 br  = *(const float2*)(b_ir + c0);
    float2 bi  = *(const float2*)(b_ii + c0);
    float2 bn  = *(const float2*)(b_in + c0);

    float d0 = dec_t[row * 3 + 0], d1 = dec_t[row * 3 + 1], d2 = dec_t[row * 3 + 2];
    float2 rsum = make_float2(0.f, 0.f), isum = make_float2(0.f, 0.f), nsum = make_float2(0.f, 0.f);
#pragma unroll
    for (int jj = 0; jj < 3; jj++) {
        float dv = (jj == 0) ? d0 : (jj == 1) ? d1 : d2;
        float2 wr = *(const float2*)(w_ir + (128 + jj) * 128 + c0);
        float2 wi = *(const float2*)(w_ii + (128 + jj) * 128 + c0);
        float2 wn = *(const float2*)(w_in + (128 + jj) * 128 + c0);
        rsum.x = fmaf(dv, wr.x, rsum.x); rsum.y = fmaf(dv, wr.y, rsum.y);
        isum.x = fmaf(dv, wi.x, isum.x); isum.y = fmaf(dv, wi.y, isum.y);
        nsum.x = fmaf(dv, wn.x, nsum.x); nsum.y = fmaf(dv, wn.y, nsum.y);
    }

    float rr0 = 1.f / (1.f + expf(-(Gr.x + rsum.x + br.x)));
    float rr1 = 1.f / (1.f + expf(-(Gr.y + rsum.y + br.y)));
    float ii0 = 1.f / (1.f + expf(-(Gi.x + isum.x + bi.x)));
    float ii1 = 1.f / (1.f + expf(-(Gi.y + isum.y + bi.y)));
    float nn0 = tanhf(Gn1.x + nsum.x + bn.x + rr0 * Gn2.x);
    float nn1 = tanhf(Gn1.y + nsum.y + bn.y + rr1 * Gn2.y);
    float hv0 = (1.f - ii0) * nn0 + ii0 * h.x;
    float hv1 = (1.f - ii1) * nn1 + ii1 * h.y;

    *(float2*)(g_x + row * 128 + c0)   = make_float2(hv0, hv1);
    *(float2*)(out_t + row * 128 + c0) = make_float2(hv0, hv1);
    if (state) *(float2*)(state + row * 128 + c0) = make_float2(hv0, hv1);

    uint32_t hi, lo;
    bf16split(hv0, hv1, hi, lo);
    g_Ahi[row * 64 + cp] = hi;
    g_Alo[row * 64 + cp] = lo;
}

// ---------------------------------------------------------------------------
// MLP phase (coalesced layers) + pack x into g_Ahi/g_Alo. rows cta*4..+3.
// ---------------------------------------------------------------------------
template<int K1>
__device__ void mlp_phase(int cta, int tid, const float* __restrict__ in,
                          const float* __restrict__ w1, const float* __restrict__ b1,
                          const float* __restrict__ w2, const float* __restrict__ b2,
                          uint32_t* sm)
{
    float* in_s = (float*)sm;          // [4][K1]
    float* hid  = in_s + 4 * K1;       // [4][256]
    float* xs   = hid + 4 * 256;       // [4][128]

    const int row0 = cta * 4;
    for (int idx = tid; idx < 4 * K1; idx += 256)
        in_s[idx] = in[row0 * K1 + idx];
    __syncthreads();

    {
        const int j = tid;
        float acc[4] = {0.f, 0.f, 0.f, 0.f};
#pragma unroll 8
        for (int k = 0; k < K1; k++) {
            float w = w1[k * EH + j];
#pragma unroll
            for (int r = 0; r < 4; r++) acc[r] = fmaf(in_s[r * K1 + k], w, acc[r]);
        }
        float bb = b1[j];
#pragma unroll
        for (int r = 0; r < 4; r++) hid[r * 256 + j] = fmaxf(acc[r] + bb, 0.f);
    }
    __syncthreads();

    {
        const int c = tid & 127, g2 = tid >> 7;
        float acc[2] = {0.f, 0.f};
#pragma unroll 8
        for (int k = 0; k < EH; k++) {
            float w = w2[k * NO + c];
#pragma unroll
            for (int r = 0; r < 2; r++) acc[r] = fmaf(hid[(g2 * 2 + r) * 256 + k], w, acc[r]);
        }
        float bb = b2[c];
#pragma unroll
        for (int r = 0; r < 2; r++) {
            float o = fmaxf(acc[r] + bb, 0.f);
            xs[(g2 * 2 + r) * 128 + c] = o;
            g_x[(row0 + g2 * 2 + r) * NO + c] = o;
        }
    }
    __syncthreads();

    {
        int r = tid >> 6, cp = tid & 63;
        float2 x = *(const float2*)(xs + r * 128 + 2 * cp);
        uint32_t hi, lo;
        bf16split(x.x, x.y, hi, lo);
        g_Ahi[(row0 + r) * 64 + cp] = hi;
        g_Alo[(row0 + r) * 64 + cp] = lo;
    }
}

// ---------------------------------------------------------------------------
// Single persistent kernel. After packing, all sync is per batch-group.
// ---------------------------------------------------------------------------
__global__ __launch_bounds__(256, 1) void fused_kernel(
    const float* __restrict__ enc_in, const float* __restrict__ dec_in,
    const float* __restrict__ enc_w1, const float* __restrict__ enc_b1,
    const float* __restrict__ enc_w2, const float* __restrict__ enc_b2,
    const float* __restrict__ pe_w1,  const float* __restrict__ pe_b1,
    const float* __restrict__ pe_w2,  const float* __restrict__ pe_b2,
    const float* __restrict__ pn_w1,  const float* __restrict__ pn_b1,
    const float* __restrict__ pn_w2,  const float* __restrict__ pn_b2,
    const float* __restrict__ de_w1,  const float* __restrict__ de_b1,
    const float* __restrict__ de_w2,  const float* __restrict__ de_b2,
    const float* __restrict__ w_hr, const float* __restrict__ w_hi,
    const float* __restrict__ w_hn,
    const float* __restrict__ w_ir, const float* __restrict__ b_ir,
    const float* __restrict__ w_ii, const float* __restrict__ b_ii,
    const float* __restrict__ w_in, const float* __restrict__ b_in,
    float* __restrict__ out, float* __restrict__ state)
{
    extern __shared__ uint32_t sm[];
    const int cta = blockIdx.x;
    const int tid = threadIdx.x;
    unsigned gen = g_bar_gen;

    // ---- phase 0: weight packing ----
    {
        int gid = cta * 256 + tid;   // 0..32767
        {
            int mat = gid >> 14, rem = gid & 16383;
            int r = rem >> 7, n = rem & 127;
            const float* W = mat ? de_w2 : pe_w2;
            uint32_t hi, lo;
            bf16split(W[(2 * r) * 128 + n], W[(2 * r + 1) * 128 + n], hi, lo);
            g_Whi[mat][r * 128 + n] = hi;
            g_Wlo[mat][r * 128 + n] = lo;
        }
#pragma unroll
        for (int i = 0; i < 2; i++) {
            int t = gid + i * 32768;
            int kp = t >> 9, n = t & 511;
            int blk = n >> 7, nn = n & 127;
            int k0 = 2 * kp, k1 = 2 * kp + 1;
            const float* Wm; const float* Wh;
            if (blk == 0) { Wm = w_ir; Wh = w_hr; }
            else if (blk == 1) { Wm = w_ii; Wh = w_hi; }
            else if (blk == 2) { Wm = w_in; Wh = nullptr; }
            else { Wm = nullptr; Wh = w_hn; }
            float v0 = (k0 < 128) ? (Wm ? Wm[k0 * 128 + nn] : 0.f)
                                  : (Wh ? Wh[(k0 - 128) * 128 + nn] : 0.f);
            float v1 = (k1 < 128) ? (Wm ? Wm[k1 * 128 + nn] : 0.f)
                                  : (Wh ? Wh[(k1 - 128) * 128 + nn] : 0.f);
            uint32_t hi, lo;
            bf16split(v0, v1, hi, lo);
            g_Wghi[kp * 512 + n] = hi;
            g_Wglo[kp * 512 + n] = lo;
        }
#pragma unroll
        for (int i = 0; i < 2; i++) {
            int t = gid + i * 32768;
            int mat = t >> 15, rem = t & 32767;
            int kp = rem >> 9, n = rem & 511;
            const float* W1 = mat ? de_w1 : pe_w1;
            int k0 = 2 * kp, k1 = 2 * kp + 1;
            float v0 = (n < 256) ? W1[k0 * 256 + n] : W1[(128 + k0) * 256 + (n - 256)];
            float v1 = (n < 256) ? W1[k1 * 256 + n] : W1[(128 + k1) * 256 + (n - 256)];
            uint32_t hi, lo;
            bf16split(v0, v1, hi, lo);
            g_Wpqhi[mat][kp * 512 + n] = hi;
            g_Wpqlo[mat][kp * 512 + n] = lo;
        }
    }
    grid_sync(gen);

    const int b    = cta >> 3;
    const int gcta = cta & 7;
    unsigned ggen = g_grp_gen[b];

    // ---- encoder mlp1, then P/Q (pe) ----
    mlp_phase<150>(cta, tid, enc_in, enc_w1, enc_b1, enc_w2, enc_b2, sm);
    group_sync(b, ggen);
    pq_phase_g(b, gcta, tid, 0, sm);
    group_sync(b, ggen);

    // ---- two message-passing rounds ----
    for (int p = 0; p < 2; p++) {
        edge_phase(cta, tid, 0, pe_b1, pe_b2, sm);
        group_sync(b, ggen);
        mlp_phase<128>(cta, tid, g_msg, pn_w1, pn_b1, pn_w2, pn_b2, sm);
        group_sync(b, ggen);
        pq_phase_g(b, gcta, tid, (p == 0) ? 0 : 1, sm);
        group_sync(b, ggen);
    }

    // ---- decoder: 25 GRU steps (all group-local) ----
    for (int t = 0; t < TSTEPS; t++) {
        edge_phase(cta, tid, 1, de_b1, de_b2, sm);
        group_sync(b, ggen);
        gates_phase_g(b, gcta, tid, sm);
        group_sync(b, ggen);
        elem_phase_g(b, gcta, tid, dec_in + (size_t)t * NROWS * 3,
                     w_ir, b_ir, w_ii, b_ii, w_in, b_in,
                     out + (size_t)t * NROWS * NO,
                     (t == TSTEPS - 1) ? state : nullptr);
        group_sync(b, ggen);
        if (t != TSTEPS - 1) {
            pq_phase_g(b, gcta, tid, 1, sm);
            group_sync(b, ggen);
        }
    }
}

// ---------------------------------------------------------------------------
extern "C" void kernel_launch(void* const* d_in, const int* in_sizes, int n_in,
                              void* d_out, int out_size)
{
    const float* enc_in = (const float*)d_in[0];
    const float* dec_in = (const float*)d_in[1];
    const float* enc_w1 = (const float*)d_in[4];
    const float* enc_b1 = (const float*)d_in[5];
    const float* enc_w2 = (const float*)d_in[6];
    const float* enc_b2 = (const float*)d_in[7];
    const float* pe_w1  = (const float*)d_in[8];
    const float* pe_b1  = (const float*)d_in[9];
    const float* pe_w2  = (const float*)d_in[10];
    const float* pe_b2  = (const float*)d_in[11];
    const float* pn_w1  = (const float*)d_in[12];
    const float* pn_b1  = (const float*)d_in[13];
    const float* pn_w2  = (const float*)d_in[14];
    const float* pn_b2  = (const float*)d_in[15];
    const float* de_w1  = (const float*)d_in[16];
    const float* de_b1  = (const float*)d_in[17];
    const float* de_w2  = (const float*)d_in[18];
    const float* de_b2  = (const float*)d_in[19];
    const float* w_hr   = (const float*)d_in[20];
    const float* w_hi   = (const float*)d_in[21];
    const float* w_hn   = (const float*)d_in[22];
    const float* w_ir   = (const float*)d_in[23];
    const float* b_ir   = (const float*)d_in[24];
    const float* w_ii   = (const float*)d_in[25];
    const float* b_ii   = (const float*)d_in[26];
    const float* w_in   = (const float*)d_in[27];
    const float* b_in   = (const float*)d_in[28];

    float* out   = (float*)d_out;
    float* state = out + (size_t)TSTEPS * NROWS * NO;

    cudaFuncSetAttribute(fused_kernel,
                         cudaFuncAttributeMaxDynamicSharedMemorySize,
                         SMEM_BYTES);

    fused_kernel<<<GRID, 256, SMEM_BYTES>>>(
        enc_in, dec_in,
        enc_w1, enc_b1, enc_w2, enc_b2,
        pe_w1, pe_b1, pe_w2, pe_b2,
        pn_w1, pn_b1, pn_w2, pn_b2,
        de_w1, de_b1, de_w2, de_b2,
        w_hr, w_hi, w_hn,
        w_ir, b_ir, w_ii, b_ii, w_in, b_in,
        out, state);
}

// round 14
// speedup vs baseline: 2.1359x; 1.0778x over previous
#include <cuda_runtime.h>
#include <cuda_bf16.h>
#include <math.h>
#include <stdint.h>

// Problem constants
#define NROWS 512      // B*N = 16*32
#define NO 128         // node out dim
#define EH 256         // edge/node hidden dim
#define TSTEPS 25
#define GRID 128       // persistent CTAs (<= 148 SMs -> all resident)
#define NTHR 512       // 16 warps per CTA
#define NGRP 16        // one group of 8 CTAs per batch element

// Scratch (device globals: no allocation allowed)
__device__ float g_x[NROWS * NO];        // node features / GRU hidden
__device__ float g_P[NROWS * EH];
__device__ float g_Q[NROWS * EH];
__device__ float g_msg[NROWS * NO];
__device__ uint32_t g_Whi[2][128 * 128]; // edge W2 bf16 hi, [kp][128]
__device__ uint32_t g_Wlo[2][128 * 128];
__device__ uint32_t g_Wghi[128 * 512];   // GRU gate W [kp][512], col' = c*4+gate
__device__ uint32_t g_Wglo[128 * 512];
__device__ uint32_t g_Wpqhi[2][64 * 512]; // P/Q W [kp][512]: [P|Q]
__device__ uint32_t g_Wpqlo[2][64 * 512];
__device__ uint32_t g_Ahi[NROWS * 64];    // packed activations (bf16x2 kpairs)
__device__ uint32_t g_Alo[NROWS * 64];

// ---------------------------------------------------------------------------
// Barriers: one grid barrier after packing, then 8-CTA group barriers.
// ---------------------------------------------------------------------------
__device__ unsigned g_bar_arrive = 0;
__device__ volatile unsigned g_bar_gen = 0;
__device__ unsigned g_grp_arrive[NGRP];
__device__ volatile unsigned g_grp_gen[NGRP];

__device__ __forceinline__ void grid_sync(unsigned &gen) {
    __threadfence();
    __syncthreads();
    if (threadIdx.x == 0) {
        unsigned old = atomicInc(&g_bar_arrive, GRID - 1);
        if (old == GRID - 1) g_bar_gen = gen + 1;
        else while (g_bar_gen == gen) { }
    }
    __syncthreads();
    gen++;
}

__device__ __forceinline__ void group_sync(int grp, unsigned &gen) {
    __threadfence();
    __syncthreads();
    if (threadIdx.x == 0) {
        unsigned old = atomicInc(&g_grp_arrive[grp], 7);
        if (old == 7) g_grp_gen[grp] = gen + 1;
        else while (g_grp_gen[grp] == gen) { }
    }
    __syncthreads();
    gen++;
}

#define CP_ASYNC16(dst, src) \
    asm volatile("cp.async.cg.shared.global [%0], [%1], 16;" :: "r"(dst), "l"(src))
#define CP_COMMIT() asm volatile("cp.async.commit_group;")
#define CP_WAIT1()  asm volatile("cp.async.wait_group 1;")
#define CP_WAIT0()  asm volatile("cp.async.wait_group 0;")

__device__ __forceinline__ void bf16split(float a0, float a1,
                                          uint32_t &hi, uint32_t &lo) {
    __nv_bfloat162 h2 = __floats2bfloat162_rn(a0, a1);
    float l0 = a0 - __low2float(h2);
    float l1 = a1 - __high2float(h2);
    __nv_bfloat162 l2 = __floats2bfloat162_rn(l0, l1);
    hi = *reinterpret_cast<uint32_t*>(&h2);
    lo = *reinterpret_cast<uint32_t*>(&l2);
}

__device__ __forceinline__ void mma_bf16(float (&d)[4], const uint32_t (&a)[4],
                                         uint32_t b0, uint32_t b1)
{
    asm volatile(
        "mma.sync.aligned.m16n8k16.row.col.f32.bf16.bf16.f32 "
        "{%0,%1,%2,%3}, {%4,%5,%6,%7}, {%8,%9}, {%0,%1,%2,%3};"
        : "+f"(d[0]), "+f"(d[1]), "+f"(d[2]), "+f"(d[3])
        : "r"(a[0]), "r"(a[1]), "r"(a[2]), "r"(a[3]), "r"(b0), "r"(b1));
}

// Shared memory (u32): edge sA [2][128][132] | sB 2x8704 | tail 2304
#define SB_OFF (2*128*132)
#define TAIL_OFF (SB_OFF + 2*8704)
#define SMEM_U32 (TAIL_OFF + 2304)
#define SMEM_BYTES (SMEM_U32 * 4)   // ~214 KB

// ---------------------------------------------------------------------------
// Edge phase: CTA = (b, 4 receivers). M=128, N=128, K=256, bf16 hi/lo 3-MMA.
// 16 warps: mtile = warp>>1 (16 rows), colhalf = warp&1 (64 cols, j=0..7).
// ---------------------------------------------------------------------------
__device__ void edge_phase(int cta, int tid, int mat,
                           const float* __restrict__ b1,
                           const float* __restrict__ b2, uint32_t* sm)
{
    uint32_t* sA = sm;                     // hi [128][132], lo at +128*132
    uint32_t* sB = sm + SB_OFF;            // 2 bufs x 8704
    float*    qb = (float*)(sm + TAIL_OFF);   // [4][256]
    float*    red = qb + 1024;                // [8][128]

    const int b   = cta >> 3;
    const int r0  = (cta & 7) * 4;
    const int bn0 = b * 32 + r0;

    const uint32_t* gWhi = g_Whi[mat];
    const uint32_t* gWlo = g_Wlo[mat];
    const uint32_t sB_base = (uint32_t)__cvta_generic_to_shared(sB);

    auto stage = [&](int ch, int buf) {
#pragma unroll
        for (int i = 0; i < 4; i++) {
            int lin = tid + i * NTHR;
            int split = lin >> 10;
            int rem = lin & 1023;
            int r = rem >> 5, c4 = rem & 31;
            const uint32_t* src = (split ? gWlo : gWhi) + ch * 32 * 128 + r * 128 + c4 * 4;
            uint32_t dst = sB_base + (uint32_t)(buf * 8704 + split * 4352 + r * 136 + c4 * 4) * 4u;
            CP_ASYNC16(dst, src);
        }
        CP_COMMIT();
    };

    stage(0, 0);

#pragma unroll
    for (int i = 0; i < 2; i++) {
        int idx = tid + i * NTHR;
        int r = idx >> 8, k = idx & 255;
        qb[idx] = g_Q[(bn0 + r) * EH + k] + b1[k];
    }
    __syncthreads();

#pragma unroll 4
    for (int i = 0; i < 32; i++) {
        int lin = tid + i * NTHR;
        int row = lin >> 7, kp = lin & 127;
        int recv = row >> 5, send = row & 31;
        float2 p = *(const float2*)(g_P + (b * 32 + send) * EH + 2 * kp);
        float2 q = *(const float2*)(qb + recv * 256 + 2 * kp);
        float a0 = fmaxf(p.x + q.x, 0.f);
        float a1 = fmaxf(p.y + q.y, 0.f);
        uint32_t hi, lo;
        bf16split(a0, a1, hi, lo);
        sA[row * 132 + kp]             = hi;
        sA[128 * 132 + row * 132 + kp] = lo;
    }

    const int lane = tid & 31;
    const int warp = tid >> 5;
    const int g    = lane >> 2;
    const int tg   = lane & 3;
    const int mtile   = warp >> 1;   // 0..7
    const int colhalf = warp & 1;
    const int lrow = mtile * 16 + (lane & 7) + ((lane >> 3) & 1) * 8;
    const int lkof = ((lane >> 4) & 1) * 4;
    const uint32_t sA_base = (uint32_t)__cvta_generic_to_shared(sA);

    float acc[8][4];
#pragma unroll
    for (int j = 0; j < 8; j++)
#pragma unroll
        for (int r = 0; r < 4; r++) acc[j][r] = 0.f;

    for (int ch = 0; ch < 4; ch++) {
        if (ch < 3) { stage(ch + 1, (ch + 1) & 1); CP_WAIT1(); }
        else        { CP_WAIT0(); }
        __syncthreads();
        uint32_t* sBuf = sB + (ch & 1) * 8704;

#pragma unroll
        for (int t = 0; t < 4; t++) {
            const int kq = (ch * 4 + t) * 8;
            uint32_t ah[4], al[4];
            {
                uint32_t addr = sA_base + (uint32_t)(lrow * 132 + kq + lkof) * 4u;
                asm volatile("ldmatrix.sync.aligned.m8n8.x4.shared.b16 {%0,%1,%2,%3}, [%4];"
                    : "=r"(ah[0]), "=r"(ah[1]), "=r"(ah[2]), "=r"(ah[3]) : "r"(addr));
                addr += 128u * 132u * 4u;
                asm volatile("ldmatrix.sync.aligned.m8n8.x4.shared.b16 {%0,%1,%2,%3}, [%4];"
                    : "=r"(al[0]), "=r"(al[1]), "=r"(al[2]), "=r"(al[3]) : "r"(addr));
            }
            const int rb0 = (t * 8 + tg) * 136;
            const int rb1 = (t * 8 + 4 + tg) * 136;
#pragma unroll
            for (int j = 0; j < 8; j++) {
                int col = colhalf * 64 + j * 8 + g;
                uint32_t bh0 = sBuf[rb0 + col];
                uint32_t bh1 = sBuf[rb1 + col];
                uint32_t bl0 = sBuf[4352 + rb0 + col];
                uint32_t bl1 = sBuf[4352 + rb1 + col];
                mma_bf16(acc[j], ah, bh0, bh1);
                mma_bf16(acc[j], al, bh0, bh1);
                mma_bf16(acc[j], ah, bl0, bl1);
            }
        }
        __syncthreads();
    }

    // Epilogue: bias + ReLU + self-edge exclusion + sender-sum (mean over 31)
    const int recvL = mtile >> 1;
    const int nrecv = r0 + recvL;
    const int sendA = (mtile & 1) * 16 + g;
    const int sendB = sendA + 8;
    float t0[8], t1[8];
#pragma unroll
    for (int j = 0; j < 8; j++) {
        int c0 = colhalf * 64 + j * 8 + 2 * tg;
        float bb0 = b2[c0], bb1 = b2[c0 + 1];
        float v00 = fmaxf(acc[j][0] + bb0, 0.f);
        float v01 = fmaxf(acc[j][1] + bb1, 0.f);
        float v10 = fmaxf(acc[j][2] + bb0, 0.f);
        float v11 = fmaxf(acc[j][3] + bb1, 0.f);
        if (sendA == nrecv) { v00 = 0.f; v01 = 0.f; }
        if (sendB == nrecv) { v10 = 0.f; v11 = 0.f; }
        t0[j] = v00 + v10;
        t1[j] = v01 + v11;
    }
#pragma unroll
    for (int off = 4; off < 32; off <<= 1) {
#pragma unroll
        for (int j = 0; j < 8; j++) {
            t0[j] += __shfl_xor_sync(0xffffffffu, t0[j], off);
            t1[j] += __shfl_xor_sync(0xffffffffu, t1[j], off);
        }
    }
    if (lane < 4) {
#pragma unroll
        for (int j = 0; j < 8; j++) {
            int c0 = colhalf * 64 + j * 8 + 2 * lane;
            red[mtile * 128 + c0]     = t0[j];
            red[mtile * 128 + c0 + 1] = t1[j];
        }
    }
    __syncthreads();
    {
        int rv = tid >> 7, c = tid & 127;
        g_msg[(bn0 + rv) * 128 + c] =
            (red[(2 * rv) * 128 + c] + red[(2 * rv + 1) * 128 + c]) * (1.0f / 31.0f);
    }
}

// ---------------------------------------------------------------------------
// M=32 x N=64 x K=(64*KCHUNKS) bf16 hi/lo GEMM mainloop.
// 16 warps: mtile = warp>>3 (16 rows), ncolq = warp&7 (8 cols, j=1): d[4].
// B from gmem [kp][512] at column ncol0, cp.async double-buffered.
// ---------------------------------------------------------------------------
template<int KCHUNKS, int PITCHA>
__device__ __forceinline__ void gemm32_mainloop(
    int tid, const uint32_t* __restrict__ Bhi, const uint32_t* __restrict__ Blo,
    int ncol0, uint32_t* sA, uint32_t* sB, float (&d)[4])
{
    const int lane = tid & 31;
    const int warp = tid >> 5;
    const int g    = lane >> 2;
    const int tg   = lane & 3;
    const int mtile = warp >> 3;
    const int ncolq = warp & 7;
    const int lrow = mtile * 16 + (lane & 7) + ((lane >> 3) & 1) * 8;
    const int lkof = ((lane >> 4) & 1) * 4;
    const uint32_t sA_base = (uint32_t)__cvta_generic_to_shared(sA);
    const uint32_t sB_base = (uint32_t)__cvta_generic_to_shared(sB);

#pragma unroll
    for (int r = 0; r < 4; r++) d[r] = 0.f;

    auto stage = [&](int ch, int buf) {
#pragma unroll
        for (int i = 0; i < 2; i++) {
            int lin = tid + i * NTHR;
            int split = lin >> 9;
            int rem = lin & 511;
            int r = rem >> 4, c4 = rem & 15;
            const uint32_t* src = (split ? Blo : Bhi) + (ch * 32 + r) * 512 + ncol0 + c4 * 4;
            uint32_t dst = sB_base + (uint32_t)(buf * 4608 + split * 2304 + r * 72 + c4 * 4) * 4u;
            CP_ASYNC16(dst, src);
        }
        CP_COMMIT();
    };

    stage(0, 0);
    for (int ch = 0; ch < KCHUNKS; ch++) {
        if (ch + 1 < KCHUNKS) { stage(ch + 1, (ch + 1) & 1); CP_WAIT1(); }
        else                  { CP_WAIT0(); }
        __syncthreads();
        uint32_t* sBuf = sB + (ch & 1) * 4608;
#pragma unroll
        for (int t = 0; t < 4; t++) {
            const int kq = (ch * 4 + t) * 8;
            uint32_t ah[4], al[4];
            {
                uint32_t addr = sA_base + (uint32_t)(lrow * PITCHA + kq + lkof) * 4u;
                asm volatile("ldmatrix.sync.aligned.m8n8.x4.shared.b16 {%0,%1,%2,%3}, [%4];"
                    : "=r"(ah[0]), "=r"(ah[1]), "=r"(ah[2]), "=r"(ah[3]) : "r"(addr));
                addr += 32u * PITCHA * 4u;
                asm volatile("ldmatrix.sync.aligned.m8n8.x4.shared.b16 {%0,%1,%2,%3}, [%4];"
                    : "=r"(al[0]), "=r"(al[1]), "=r"(al[2]), "=r"(al[3]) : "r"(addr));
            }
            const int rb0 = (t * 8 + tg) * 72;
            const int rb1 = (t * 8 + 4 + tg) * 72;
            int col = ncolq * 8 + g;
            uint32_t bh0 = sBuf[rb0 + col];
            uint32_t bh1 = sBuf[rb1 + col];
            uint32_t bl0 = sBuf[2304 + rb0 + col];
            uint32_t bl1 = sBuf[2304 + rb1 + col];
            mma_bf16(d, ah, bh0, bh1);
            mma_bf16(d, al, bh0, bh1);
            mma_bf16(d, ah, bl0, bl1);
        }
        __syncthreads();
    }
}

// ---------------------------------------------------------------------------
// Fused gates GEMM + GRU elementwise + h' pack (all in-CTA after GEMM).
// Wg columns interleaved: col' = c*4 + gate. CTA covers c = gcta*16..+15.
// ---------------------------------------------------------------------------
__device__ void gates_elem_phase(int b, int gcta, int tid,
    const float* __restrict__ dec_t,
    const float* __restrict__ w_ir, const float* __restrict__ b_ir,
    const float* __restrict__ w_ii, const float* __restrict__ b_ii,
    const float* __restrict__ w_in, const float* __restrict__ b_in,
    float* __restrict__ out_t, float* __restrict__ state, uint32_t* sm)
{
    uint32_t* sA = sm;
    uint32_t* sB = sm + SB_OFF;
    float* sG = (float*)(sm + TAIL_OFF);   // [32][68] floats (2176 <= 2304)
    float* sH = (float*)sm;                // reuse sA region post-mainloop: [32][16]
    const int m0 = b * 32;

    // Build A: [msg|h][32 rows][128 kpairs] -> bf16 hi/lo
#pragma unroll
    for (int i = 0; i < 8; i++) {
        int lin = tid + i * NTHR;
        int row = lin >> 7, kp = lin & 127;
        int grow = m0 + row;
        float2 x = (kp < 64)
            ? *(const float2*)(g_msg + grow * 128 + 2 * kp)
            : *(const float2*)(g_x + grow * 128 + 2 * (kp - 64));
        uint32_t hi, lo;
        bf16split(x.x, x.y, hi, lo);
        sA[row * 132 + kp]            = hi;
        sA[32 * 132 + row * 132 + kp] = lo;
    }

    float d[4];
    gemm32_mainloop<4, 132>(tid, g_Wghi, g_Wglo, gcta * 64, sA, sB, d);

    // Scatter GEMM result to sG
    {
        const int lane = tid & 31, warp = tid >> 5;
        const int g = lane >> 2, tg = lane & 3;
        const int mtile = warp >> 3, ncolq = warp & 7;
        int rw = mtile * 16 + g;
        int colL = ncolq * 8 + 2 * tg;
        *(float2*)(sG + rw * 68 + colL)       = make_float2(d[0], d[1]);
        *(float2*)(sG + (rw + 8) * 68 + colL) = make_float2(d[2], d[3]);
    }
    __syncthreads();

    // Elementwise GRU: thread -> (row = tid>>4, cl = tid&15); c = gcta*16+cl
    {
        int row = tid >> 4, cl = tid & 15;
        int c = gcta * 16 + cl;
        int grow = m0 + row;
        float4 G = *(const float4*)(sG + row * 68 + cl * 4);  // Gr,Gi,Gn1,Gn2
        float h = g_x[grow * 128 + c];
        float d0 = dec_t[grow * 3 + 0], d1 = dec_t[grow * 3 + 1], d2 = dec_t[grow * 3 + 2];
        float rsum = d0 * w_ir[128 * 128 + c] + d1 * w_ir[129 * 128 + c] + d2 * w_ir[130 * 128 + c];
        float isum = d0 * w_ii[128 * 128 + c] + d1 * w_ii[129 * 128 + c] + d2 * w_ii[130 * 128 + c];
        float nsum = d0 * w_in[128 * 128 + c] + d1 * w_in[129 * 128 + c] + d2 * w_in[130 * 128 + c];
        float rr = 1.f / (1.f + expf(-(G.x + rsum + b_ir[c])));
        float ii = 1.f / (1.f + expf(-(G.y + isum + b_ii[c])));
        float nn = tanhf(G.z + nsum + b_in[c] + rr * G.w);
        float hv = (1.f - ii) * nn + ii * h;
        g_x[grow * 128 + c] = hv;
        out_t[grow * 128 + c] = hv;
        if (state) state[grow * 128 + c] = hv;
        sH[row * 16 + cl] = hv;
    }
    __syncthreads();

    // Pack h' window into g_Ahi/g_Alo (32 rows x 8 kpairs)
    if (tid < 256) {
        int r2 = tid >> 3, kpl = tid & 7;
        int cp = gcta * 8 + kpl;
        float h0 = sH[r2 * 16 + 2 * kpl];
        float h1 = sH[r2 * 16 + 2 * kpl + 1];
        uint32_t hi, lo;
        bf16split(h0, h1, hi, lo);
        g_Ahi[(m0 + r2) * 64 + cp] = hi;
        g_Alo[(m0 + r2) * 64 + cp] = lo;
    }
}

// ---------------------------------------------------------------------------
// PQ phase: [P|Q][32,512] = Apk[32,128] @ Wpq[128,512]. CTA: 64 cols.
// ---------------------------------------------------------------------------
__device__ void pq_phase(int b, int gcta, int tid, int mat, uint32_t* sm)
{
    uint32_t* sA = sm;
    uint32_t* sB = sm + SB_OFF;
    const int m0 = b * 32;

#pragma unroll
    for (int i = 0; i < 2; i++) {
        int lin = tid + i * NTHR;          // 0..1023
        int split = lin >> 9;
        int rem = lin & 511;
        int row = rem >> 4, c4 = rem & 15;
        uint4 v = ((const uint4*)((split ? g_Alo : g_Ahi) + (m0 + row) * 64))[c4];
        *(uint4*)(sA + split * 32 * 68 + row * 68 + c4 * 4) = v;
    }

    float d[4];
    gemm32_mainloop<2, 68>(tid, g_Wpqhi[mat], g_Wpqlo[mat], gcta * 64, sA, sB, d);

    const int lane = tid & 31, warp = tid >> 5;
    const int g = lane >> 2, tg = lane & 3;
    const int mtile = warp >> 3, ncolq = warp & 7;
    const int gcol = gcta * 64 + ncolq * 8 + 2 * tg;
    float* dst = (gcol < 256) ? g_P : g_Q;
    const int cc = (gcol < 256) ? gcol : gcol - 256;
    int rlo = m0 + mtile * 16 + g;
    *(float2*)(dst + rlo * 256 + cc)       = make_float2(d[0], d[1]);
    *(float2*)(dst + (rlo + 8) * 256 + cc) = make_float2(d[2], d[3]);
}

// ---------------------------------------------------------------------------
// MLP phase (coalesced scalar layers) + pack x. rows cta*4..+3. 512 threads.
// ---------------------------------------------------------------------------
template<int K1>
__device__ void mlp_phase(int cta, int tid, const float* __restrict__ in,
                          const float* __restrict__ w1, const float* __restrict__ b1,
                          const float* __restrict__ w2, const float* __restrict__ b2,
                          uint32_t* sm)
{
    float* in_s = (float*)sm;          // [4][K1]
    float* hid  = in_s + 4 * K1;       // [4][256]
    float* xs   = hid + 4 * 256;       // [4][128]

    const int row0 = cta * 4;
    for (int idx = tid; idx < 4 * K1; idx += NTHR)
        in_s[idx] = in[row0 * K1 + idx];
    __syncthreads();

    // layer 1: K1 -> 256; thread = (pair = tid>>8, j = tid&255), 2 rows each
    {
        const int pr = tid >> 8, j = tid & 255;
        float acc[2] = {0.f, 0.f};
#pragma unroll 8
        for (int k = 0; k < K1; k++) {
            float w = w1[k * EH + j];
            acc[0] = fmaf(in_s[(pr * 2 + 0) * K1 + k], w, acc[0]);
            acc[1] = fmaf(in_s[(pr * 2 + 1) * K1 + k], w, acc[1]);
        }
        float bb = b1[j];
        hid[(pr * 2 + 0) * 256 + j] = fmaxf(acc[0] + bb, 0.f);
        hid[(pr * 2 + 1) * 256 + j] = fmaxf(acc[1] + bb, 0.f);
    }
    __syncthreads();

    // layer 2: 256 -> 128; thread = (row = tid>>7, c = tid&127)
    {
        const int rr = tid >> 7, c = tid & 127;
        float acc = 0.f;
#pragma unroll 8
        for (int k = 0; k < EH; k++)
            acc = fmaf(hid[rr * 256 + k], w2[k * NO + c], acc);
        float o = fmaxf(acc + b2[c], 0.f);
        xs[rr * 128 + c] = o;
        g_x[(row0 + rr) * NO + c] = o;
    }
    __syncthreads();

    if (tid < 256) {
        int r = tid >> 6, cp = tid & 63;
        float2 x = *(const float2*)(xs + r * 128 + 2 * cp);
        uint32_t hi, lo;
        bf16split(x.x, x.y, hi, lo);
        g_Ahi[(row0 + r) * 64 + cp] = hi;
        g_Alo[(row0 + r) * 64 + cp] = lo;
    }
}

// ---------------------------------------------------------------------------
// Single persistent kernel.
// ---------------------------------------------------------------------------
__global__ __launch_bounds__(NTHR, 1) void fused_kernel(
    const float* __restrict__ enc_in, const float* __restrict__ dec_in,
    const float* __restrict__ enc_w1, const float* __restrict__ enc_b1,
    const float* __restrict__ enc_w2, const float* __restrict__ enc_b2,
    const float* __restrict__ pe_w1,  const float* __restrict__ pe_b1,
    const float* __restrict__ pe_w2,  const float* __restrict__ pe_b2,
    const float* __restrict__ pn_w1,  const float* __restrict__ pn_b1,
    const float* __restrict__ pn_w2,  const float* __restrict__ pn_b2,
    const float* __restrict__ de_w1,  const float* __restrict__ de_b1,
    const float* __restrict__ de_w2,  const float* __restrict__ de_b2,
    const float* __restrict__ w_hr, const float* __restrict__ w_hi,
    const float* __restrict__ w_hn,
    const float* __restrict__ w_ir, const float* __restrict__ b_ir,
    const float* __restrict__ w_ii, const float* __restrict__ b_ii,
    const float* __restrict__ w_in, const float* __restrict__ b_in,
    float* __restrict__ out, float* __restrict__ state)
{
    extern __shared__ uint32_t sm[];
    const int cta = blockIdx.x;
    const int tid = threadIdx.x;
    unsigned gen = g_bar_gen;

    // ---- phase 0: weight packing (65536 threads) ----
    {
        int gid = cta * NTHR + tid;   // 0..65535
        if (gid < 32768) {
            int mat = gid >> 14, rem = gid & 16383;
            int r = rem >> 7, n = rem & 127;
            const float* W = mat ? de_w2 : pe_w2;
            uint32_t hi, lo;
            bf16split(W[(2 * r) * 128 + n], W[(2 * r + 1) * 128 + n], hi, lo);
            g_Whi[mat][r * 128 + n] = hi;
            g_Wlo[mat][r * 128 + n] = lo;
        }
        // Wg interleaved: col' = c*4 + gate
        {
            int kp = gid >> 9, n = gid & 511;
            int c = n >> 2, gate = n & 3;
            int k0 = 2 * kp, k1 = 2 * kp + 1;
            const float* Wm; const float* Wh;
            if (gate == 0) { Wm = w_ir; Wh = w_hr; }
            else if (gate == 1) { Wm = w_ii; Wh = w_hi; }
            else if (gate == 2) { Wm = w_in; Wh = nullptr; }
            else { Wm = nullptr; Wh = w_hn; }
            float v0 = (k0 < 128) ? (Wm ? Wm[k0 * 128 + c] : 0.f)
                                  : (Wh ? Wh[(k0 - 128) * 128 + c] : 0.f);
            float v1 = (k1 < 128) ? (Wm ? Wm[k1 * 128 + c] : 0.f)
                                  : (Wh ? Wh[(k1 - 128) * 128 + c] : 0.f);
            uint32_t hi, lo;
            bf16split(v0, v1, hi, lo);
            g_Wghi[kp * 512 + n] = hi;
            g_Wglo[kp * 512 + n] = lo;
        }
        // Wpq: [P|Q]
        {
            int mat = gid >> 15, rem = gid & 32767;
            int kp = rem >> 9, n = rem & 511;
            const float* W1 = mat ? de_w1 : pe_w1;
            int k0 = 2 * kp, k1 = 2 * kp + 1;
            float v0 = (n < 256) ? W1[k0 * 256 + n] : W1[(128 + k0) * 256 + (n - 256)];
            float v1 = (n < 256) ? W1[k1 * 256 + n] : W1[(128 + k1) * 256 + (n - 256)];
            uint32_t hi, lo;
            bf16split(v0, v1, hi, lo);
            g_Wpqhi[mat][kp * 512 + n] = hi;
            g_Wpqlo[mat][kp * 512 + n] = lo;
        }
    }
    grid_sync(gen);

    const int b    = cta >> 3;
    const int gcta = cta & 7;
    unsigned ggen = g_grp_gen[b];

    // ---- encoder mlp1, then P/Q (pe) ----
    mlp_phase<150>(cta, tid, enc_in, enc_w1, enc_b1, enc_w2, enc_b2, sm);
    group_sync(b, ggen);
    pq_phase(b, gcta, tid, 0, sm);
    group_sync(b, ggen);

    // ---- two message-passing rounds ----
    for (int p = 0; p < 2; p++) {
        edge_phase(cta, tid, 0, pe_b1, pe_b2, sm);
        group_sync(b, ggen);
        mlp_phase<128>(cta, tid, g_msg, pn_w1, pn_b1, pn_w2, pn_b2, sm);
        group_sync(b, ggen);
        pq_phase(b, gcta, tid, (p == 0) ? 0 : 1, sm);
        group_sync(b, ggen);
    }

    // ---- decoder: 25 GRU steps, 3 group barriers each ----
    for (int t = 0; t < TSTEPS; t++) {
        edge_phase(cta, tid, 1, de_b1, de_b2, sm);
        group_sync(b, ggen);
        gates_elem_phase(b, gcta, tid, dec_in + (size_t)t * NROWS * 3,
                         w_ir, b_ir, w_ii, b_ii, w_in, b_in,
                         out + (size_t)t * NROWS * NO,
                         (t == TSTEPS - 1) ? state : nullptr, sm);
        group_sync(b, ggen);
        if (t != TSTEPS - 1) {
            pq_phase(b, gcta, tid, 1, sm);
            group_sync(b, ggen);
        }
    }
}

// ---------------------------------------------------------------------------
extern "C" void kernel_launch(void* const* d_in, const int* in_sizes, int n_in,
                              void* d_out, int out_size)
{
    const float* enc_in = (const float*)d_in[0];
    const float* dec_in = (const float*)d_in[1];
    const float* enc_w1 = (const float*)d_in[4];
    const float* enc_b1 = (const float*)d_in[5];
    const float* enc_w2 = (const float*)d_in[6];
    const float* enc_b2 = (const float*)d_in[7];
    const float* pe_w1  = (const float*)d_in[8];
    const float* pe_b1  = (const float*)d_in[9];
    const float* pe_w2  = (const float*)d_in[10];
    const float* pe_b2  = (const float*)d_in[11];
    const float* pn_w1  = (const float*)d_in[12];
    const float* pn_b1  = (const float*)d_in[13];
    const float* pn_w2  = (const float*)d_in[14];
    const float* pn_b2  = (const float*)d_in[15];
    const float* de_w1  = (const float*)d_in[16];
    const float* de_b1  = (const float*)d_in[17];
    const float* de_w2  = (const float*)d_in[18];
    const float* de_b2  = (const float*)d_in[19];
    const float* w_hr   = (const float*)d_in[20];
    const float* w_hi   = (const float*)d_in[21];
    const float* w_hn   = (const float*)d_in[22];
    const float* w_ir   = (const float*)d_in[23];
    const float* b_ir   = (const float*)d_in[24];
    const float* w_ii   = (const float*)d_in[25];
    const float* b_ii   = (const float*)d_in[26];
    const float* w_in   = (const float*)d_in[27];
    const float* b_in   = (const float*)d_in[28];

    float* out   = (float*)d_out;
    float* state = out + (size_t)TSTEPS * NROWS * NO;

    cudaFuncSetAttribute(fused_kernel,
                         cudaFuncAttributeMaxDynamicSharedMemorySize,
                         SMEM_BYTES);

    fused_kernel<<<GRID, NTHR, SMEM_BYTES>>>(
        enc_in, dec_in,
        enc_w1, enc_b1, enc_w2, enc_b2,
        pe_w1, pe_b1, pe_w2, pe_b2,
        pn_w1, pn_b1, pn_w2, pn_b2,
        de_w1, de_b1, de_w2, de_b2,
        w_hr, w_hi, w_hn,
        w_ir, b_ir, w_ii, b_ii, w_in, b_in,
        out, state);
}

// round 15
// speedup vs baseline: 2.1603x; 1.0114x over previous
#include <cuda_runtime.h>
#include <cuda_bf16.h>
#include <math.h>
#include <stdint.h>

// Problem constants
#define NROWS 512      // B*N = 16*32
#define NO 128         // node out dim
#define EH 256         // edge/node hidden dim
#define TSTEPS 25
#define GRID 128       // persistent CTAs (<= 148 SMs -> all resident)
#define NTHR 512       // 16 warps per CTA
#define NGRP 16        // one group of 8 CTAs per batch element

// Scratch (device globals: no allocation allowed)
__device__ float g_x[NROWS * NO];        // node features / GRU hidden
__device__ float g_P[NROWS * EH];
__device__ float g_Q[NROWS * EH];
__device__ float g_msg[NROWS * NO];
// Interleaved bf16 hi/lo weight packs: uint4 = {hi(kp), hi(kp+4), lo(kp), lo(kp+4)}
// where hi/lo are bf16x2 of W[2kp..2kp+1][col] (hi) and the residual (lo).
__device__ uint4 g_We[2][8192];      // edge W2: [ch(4)][t(4)][tg(4)][col(128)]
__device__ uint4 g_Wg[32768];        // GRU gates: [ch(4)][t][tg][col(512)], col=c*4+gate
__device__ uint4 g_Wpq[2][16384];    // P/Q: [ch(2)][t][tg][col(512)], cols [P|Q]
__device__ uint32_t g_Ahi[NROWS * 64];    // packed activations (bf16x2 kpairs)
__device__ uint32_t g_Alo[NROWS * 64];

// ---------------------------------------------------------------------------
// Barriers: one grid barrier after packing, then 8-CTA group barriers.
// ---------------------------------------------------------------------------
__device__ unsigned g_bar_arrive = 0;
__device__ volatile unsigned g_bar_gen = 0;
__device__ unsigned g_grp_arrive[NGRP];
__device__ volatile unsigned g_grp_gen[NGRP];

__device__ __forceinline__ void grid_sync(unsigned &gen) {
    __threadfence();
    __syncthreads();
    if (threadIdx.x == 0) {
        unsigned old = atomicInc(&g_bar_arrive, GRID - 1);
        if (old == GRID - 1) g_bar_gen = gen + 1;
        else while (g_bar_gen == gen) { }
    }
    __syncthreads();
    gen++;
}

__device__ __forceinline__ void group_sync(int grp, unsigned &gen) {
    __threadfence();
    __syncthreads();
    if (threadIdx.x == 0) {
        unsigned old = atomicInc(&g_grp_arrive[grp], 7);
        if (old == 7) g_grp_gen[grp] = gen + 1;
        else while (g_grp_gen[grp] == gen) { }
    }
    __syncthreads();
    gen++;
}

#define CP_ASYNC16(dst, src) \
    asm volatile("cp.async.cg.shared.global [%0], [%1], 16;" :: "r"(dst), "l"(src))
#define CP_COMMIT() asm volatile("cp.async.commit_group;")
#define CP_WAIT1()  asm volatile("cp.async.wait_group 1;")
#define CP_WAIT0()  asm volatile("cp.async.wait_group 0;")

__device__ __forceinline__ void bf16split(float a0, float a1,
                                          uint32_t &hi, uint32_t &lo) {
    __nv_bfloat162 h2 = __floats2bfloat162_rn(a0, a1);
    float l0 = a0 - __low2float(h2);
    float l1 = a1 - __high2float(h2);
    __nv_bfloat162 l2 = __floats2bfloat162_rn(l0, l1);
    hi = *reinterpret_cast<uint32_t*>(&h2);
    lo = *reinterpret_cast<uint32_t*>(&l2);
}

__device__ __forceinline__ void mma_bf16(float (&d)[4], const uint32_t (&a)[4],
                                         uint32_t b0, uint32_t b1)
{
    asm volatile(
        "mma.sync.aligned.m16n8k16.row.col.f32.bf16.bf16.f32 "
        "{%0,%1,%2,%3}, {%4,%5,%6,%7}, {%8,%9}, {%0,%1,%2,%3};"
        : "+f"(d[0]), "+f"(d[1]), "+f"(d[2]), "+f"(d[3])
        : "r"(a[0]), "r"(a[1]), "r"(a[2]), "r"(a[3]), "r"(b0), "r"(b1));
}

// Shared memory (u32): edge sA [2][128][132] | sB 2 x 2080 uint4 | tail 2304
#define SB_OFF (2*128*132)              // 33792 u32
#define SB_U32 (2*2080*4)               // 16640 u32
#define TAIL_OFF (SB_OFF + SB_U32)
#define SMEM_U32 (TAIL_OFF + 2304)
#define SMEM_BYTES (SMEM_U32 * 4)       // ~211 KB

// ---------------------------------------------------------------------------
// Edge phase: CTA = (b, 4 receivers). M=128, N=128, K=256, bf16 hi/lo 3-MMA.
// B fragments load as ONE LDS.128 per (kstep, j): uint4 {bh0,bh1,bl0,bl1}.
// ---------------------------------------------------------------------------
__device__ void edge_phase(int cta, int tid, int mat,
                           const float* __restrict__ b1,
                           const float* __restrict__ b2, uint32_t* sm)
{
    uint32_t* sA = sm;                        // hi [128][132], lo at +128*132
    uint32_t* sB = sm + SB_OFF;               // 2 bufs x 2080 uint4 (pitch 130)
    float*    qb = (float*)(sm + TAIL_OFF);   // [4][256]
    float*    red = qb + 1024;                // [8][128]

    const int b   = cta >> 3;
    const int r0  = (cta & 7) * 4;
    const int bn0 = b * 32 + r0;

    const uint4* gW = g_We[mat];
    const uint32_t sB_byte = (uint32_t)__cvta_generic_to_shared(sB);

    auto stage = [&](int ch, int buf) {
#pragma unroll
        for (int i = 0; i < 4; i++) {
            int lin = tid + i * NTHR;           // 0..2047
            int row = lin >> 7, col = lin & 127;
            const uint4* src = gW + ch * 2048 + lin;
            uint32_t dst = sB_byte + (uint32_t)(buf * 2080 + row * 130 + col) * 16u;
            CP_ASYNC16(dst, src);
        }
        CP_COMMIT();
    };

    stage(0, 0);

#pragma unroll
    for (int i = 0; i < 2; i++) {
        int idx = tid + i * NTHR;
        int r = idx >> 8, k = idx & 255;
        qb[idx] = g_Q[(bn0 + r) * EH + k] + b1[k];
    }
    __syncthreads();

#pragma unroll 4
    for (int i = 0; i < 32; i++) {
        int lin = tid + i * NTHR;
        int row = lin >> 7, kp = lin & 127;
        int recv = row >> 5, send = row & 31;
        float2 p = *(const float2*)(g_P + (b * 32 + send) * EH + 2 * kp);
        float2 q = *(const float2*)(qb + recv * 256 + 2 * kp);
        float a0 = fmaxf(p.x + q.x, 0.f);
        float a1 = fmaxf(p.y + q.y, 0.f);
        uint32_t hi, lo;
        bf16split(a0, a1, hi, lo);
        sA[row * 132 + kp]             = hi;
        sA[128 * 132 + row * 132 + kp] = lo;
    }

    const int lane = tid & 31;
    const int warp = tid >> 5;
    const int g    = lane >> 2;
    const int tg   = lane & 3;
    const int mtile   = warp >> 1;   // 0..7
    const int colhalf = warp & 1;
    const int lrow = mtile * 16 + (lane & 7) + ((lane >> 3) & 1) * 8;
    const int lkof = ((lane >> 4) & 1) * 4;
    const uint32_t sA_base = (uint32_t)__cvta_generic_to_shared(sA);

    float acc[8][4];
#pragma unroll
    for (int j = 0; j < 8; j++)
#pragma unroll
        for (int r = 0; r < 4; r++) acc[j][r] = 0.f;

    for (int ch = 0; ch < 4; ch++) {
        if (ch < 3) { stage(ch + 1, (ch + 1) & 1); CP_WAIT1(); }
        else        { CP_WAIT0(); }
        __syncthreads();
        const uint4* sBuf4 = (const uint4*)sB + (ch & 1) * 2080;

#pragma unroll
        for (int t = 0; t < 4; t++) {
            const int kq = (ch * 4 + t) * 8;
            uint32_t ah[4], al[4];
            {
                uint32_t addr = sA_base + (uint32_t)(lrow * 132 + kq + lkof) * 4u;
                asm volatile("ldmatrix.sync.aligned.m8n8.x4.shared.b16 {%0,%1,%2,%3}, [%4];"
                    : "=r"(ah[0]), "=r"(ah[1]), "=r"(ah[2]), "=r"(ah[3]) : "r"(addr));
                addr += 128u * 132u * 4u;
                asm volatile("ldmatrix.sync.aligned.m8n8.x4.shared.b16 {%0,%1,%2,%3}, [%4];"
                    : "=r"(al[0]), "=r"(al[1]), "=r"(al[2]), "=r"(al[3]) : "r"(addr));
            }
            const uint4* brow = sBuf4 + (t * 4 + tg) * 130 + colhalf * 64 + g;
#pragma unroll
            for (int j = 0; j < 8; j++) {
                uint4 bv = brow[j * 8];
                mma_bf16(acc[j], ah, bv.x, bv.y);
                mma_bf16(acc[j], al, bv.x, bv.y);
                mma_bf16(acc[j], ah, bv.z, bv.w);
            }
        }
        __syncthreads();
    }

    // Epilogue: bias + ReLU + self-edge exclusion + sender-sum (mean over 31)
    const int recvL = mtile >> 1;
    const int nrecv = r0 + recvL;
    const int sendA = (mtile & 1) * 16 + g;
    const int sendB = sendA + 8;
    float t0[8], t1[8];
#pragma unroll
    for (int j = 0; j < 8; j++) {
        int c0 = colhalf * 64 + j * 8 + 2 * tg;
        float bb0 = b2[c0], bb1 = b2[c0 + 1];
        float v00 = fmaxf(acc[j][0] + bb0, 0.f);
        float v01 = fmaxf(acc[j][1] + bb1, 0.f);
        float v10 = fmaxf(acc[j][2] + bb0, 0.f);
        float v11 = fmaxf(acc[j][3] + bb1, 0.f);
        if (sendA == nrecv) { v00 = 0.f; v01 = 0.f; }
        if (sendB == nrecv) { v10 = 0.f; v11 = 0.f; }
        t0[j] = v00 + v10;
        t1[j] = v01 + v11;
    }
#pragma unroll
    for (int off = 4; off < 32; off <<= 1) {
#pragma unroll
        for (int j = 0; j < 8; j++) {
            t0[j] += __shfl_xor_sync(0xffffffffu, t0[j], off);
            t1[j] += __shfl_xor_sync(0xffffffffu, t1[j], off);
        }
    }
    if (lane < 4) {
#pragma unroll
        for (int j = 0; j < 8; j++) {
            int c0 = colhalf * 64 + j * 8 + 2 * lane;
            red[mtile * 128 + c0]     = t0[j];
            red[mtile * 128 + c0 + 1] = t1[j];
        }
    }
    __syncthreads();
    {
        int rv = tid >> 7, c = tid & 127;
        g_msg[(bn0 + rv) * 128 + c] =
            (red[(2 * rv) * 128 + c] + red[(2 * rv + 1) * 128 + c]) * (1.0f / 31.0f);
    }
}

// ---------------------------------------------------------------------------
// M=32 x N=64 x K=(64*KCHUNKS) bf16 hi/lo GEMM mainloop.
// 16 warps: mtile = warp>>3 (16 rows), ncolq = warp&7 (8 cols): d[4].
// B from interleaved-uint4 gmem [ch*16+row][512] at column ncol0.
// ---------------------------------------------------------------------------
template<int KCHUNKS, int PITCHA>
__device__ __forceinline__ void gemm32_mainloop(
    int tid, const uint4* __restrict__ Bq,
    int ncol0, uint32_t* sA, uint32_t* sB, float (&d)[4])
{
    const int lane = tid & 31;
    const int warp = tid >> 5;
    const int g    = lane >> 2;
    const int tg   = lane & 3;
    const int mtile = warp >> 3;
    const int ncolq = warp & 7;
    const int lrow = mtile * 16 + (lane & 7) + ((lane >> 3) & 1) * 8;
    const int lkof = ((lane >> 4) & 1) * 4;
    const uint32_t sA_base = (uint32_t)__cvta_generic_to_shared(sA);
    const uint32_t sB_byte = (uint32_t)__cvta_generic_to_shared(sB);

#pragma unroll
    for (int r = 0; r < 4; r++) d[r] = 0.f;

    auto stage = [&](int ch, int buf) {
#pragma unroll
        for (int i = 0; i < 2; i++) {
            int lin = tid + i * NTHR;           // 0..1023
            int row = lin >> 6, col = lin & 63;
            const uint4* src = Bq + (ch * 16 + row) * 512 + ncol0 + col;
            uint32_t dst = sB_byte + (uint32_t)(buf * 1056 + row * 66 + col) * 16u;
            CP_ASYNC16(dst, src);
        }
        CP_COMMIT();
    };

    stage(0, 0);
    for (int ch = 0; ch < KCHUNKS; ch++) {
        if (ch + 1 < KCHUNKS) { stage(ch + 1, (ch + 1) & 1); CP_WAIT1(); }
        else                  { CP_WAIT0(); }
        __syncthreads();
        const uint4* sBuf4 = (const uint4*)sB + (ch & 1) * 1056;
#pragma unroll
        for (int t = 0; t < 4; t++) {
            const int kq = (ch * 4 + t) * 8;
            uint32_t ah[4], al[4];
            {
                uint32_t addr = sA_base + (uint32_t)(lrow * PITCHA + kq + lkof) * 4u;
                asm volatile("ldmatrix.sync.aligned.m8n8.x4.shared.b16 {%0,%1,%2,%3}, [%4];"
                    : "=r"(ah[0]), "=r"(ah[1]), "=r"(ah[2]), "=r"(ah[3]) : "r"(addr));
                addr += 32u * PITCHA * 4u;
                asm volatile("ldmatrix.sync.aligned.m8n8.x4.shared.b16 {%0,%1,%2,%3}, [%4];"
                    : "=r"(al[0]), "=r"(al[1]), "=r"(al[2]), "=r"(al[3]) : "r"(addr));
            }
            uint4 bv = sBuf4[(t * 4 + tg) * 66 + ncolq * 8 + g];
            mma_bf16(d, ah, bv.x, bv.y);
            mma_bf16(d, al, bv.x, bv.y);
            mma_bf16(d, ah, bv.z, bv.w);
        }
        __syncthreads();
    }
}

// ---------------------------------------------------------------------------
// Fused gates GEMM + GRU elementwise + h' pack.
// Wg columns interleaved: col' = c*4 + gate. CTA covers c = gcta*16..+15.
// ---------------------------------------------------------------------------
__device__ void gates_elem_phase(int b, int gcta, int tid,
    const float* __restrict__ dec_t,
    const float* __restrict__ w_ir, const float* __restrict__ b_ir,
    const float* __restrict__ w_ii, const float* __restrict__ b_ii,
    const float* __restrict__ w_in, const float* __restrict__ b_in,
    float* __restrict__ out_t, float* __restrict__ state, uint32_t* sm)
{
    uint32_t* sA = sm;
    uint32_t* sB = sm + SB_OFF;
    float* sG = (float*)(sm + TAIL_OFF);   // [32][68] floats (2176 <= 2304)
    float* sH = (float*)sm;                // reuse sA region post-mainloop
    const int m0 = b * 32;

#pragma unroll
    for (int i = 0; i < 8; i++) {
        int lin = tid + i * NTHR;
        int row = lin >> 7, kp = lin & 127;
        int grow = m0 + row;
        float2 x = (kp < 64)
            ? *(const float2*)(g_msg + grow * 128 + 2 * kp)
            : *(const float2*)(g_x + grow * 128 + 2 * (kp - 64));
        uint32_t hi, lo;
        bf16split(x.x, x.y, hi, lo);
        sA[row * 132 + kp]            = hi;
        sA[32 * 132 + row * 132 + kp] = lo;
    }

    float d[4];
    gemm32_mainloop<4, 132>(tid, g_Wg, gcta * 64, sA, sB, d);

    {
        const int lane = tid & 31, warp = tid >> 5;
        const int g = lane >> 2, tg = lane & 3;
        const int mtile = warp >> 3, ncolq = warp & 7;
        int rw = mtile * 16 + g;
        int colL = ncolq * 8 + 2 * tg;
        *(float2*)(sG + rw * 68 + colL)       = make_float2(d[0], d[1]);
        *(float2*)(sG + (rw + 8) * 68 + colL) = make_float2(d[2], d[3]);
    }
    __syncthreads();

    {
        int row = tid >> 4, cl = tid & 15;
        int c = gcta * 16 + cl;
        int grow = m0 + row;
        float4 G = *(const float4*)(sG + row * 68 + cl * 4);  // Gr,Gi,Gn1,Gn2
        float h = g_x[grow * 128 + c];
        float d0 = dec_t[grow * 3 + 0], d1 = dec_t[grow * 3 + 1], d2 = dec_t[grow * 3 + 2];
        float rsum = d0 * w_ir[128 * 128 + c] + d1 * w_ir[129 * 128 + c] + d2 * w_ir[130 * 128 + c];
        float isum = d0 * w_ii[128 * 128 + c] + d1 * w_ii[129 * 128 + c] + d2 * w_ii[130 * 128 + c];
        float nsum = d0 * w_in[128 * 128 + c] + d1 * w_in[129 * 128 + c] + d2 * w_in[130 * 128 + c];
        float rr = 1.f / (1.f + expf(-(G.x + rsum + b_ir[c])));
        float ii = 1.f / (1.f + expf(-(G.y + isum + b_ii[c])));
        float nn = tanhf(G.z + nsum + b_in[c] + rr * G.w);
        float hv = (1.f - ii) * nn + ii * h;
        g_x[grow * 128 + c] = hv;
        out_t[grow * 128 + c] = hv;
        if (state) state[grow * 128 + c] = hv;
        sH[row * 16 + cl] = hv;
    }
    __syncthreads();

    if (tid < 256) {
        int r2 = tid >> 3, kpl = tid & 7;
        int cp = gcta * 8 + kpl;
        float h0 = sH[r2 * 16 + 2 * kpl];
        float h1 = sH[r2 * 16 + 2 * kpl + 1];
        uint32_t hi, lo;
        bf16split(h0, h1, hi, lo);
        g_Ahi[(m0 + r2) * 64 + cp] = hi;
        g_Alo[(m0 + r2) * 64 + cp] = lo;
    }
}

// ---------------------------------------------------------------------------
// PQ phase: [P|Q][32,512] = Apk[32,128] @ Wpq[128,512]. CTA: 64 cols.
// ---------------------------------------------------------------------------
__device__ void pq_phase(int b, int gcta, int tid, int mat, uint32_t* sm)
{
    uint32_t* sA = sm;
    uint32_t* sB = sm + SB_OFF;
    const int m0 = b * 32;

#pragma unroll
    for (int i = 0; i < 2; i++) {
        int lin = tid + i * NTHR;          // 0..1023
        int split = lin >> 9;
        int rem = lin & 511;
        int row = rem >> 4, c4 = rem & 15;
        uint4 v = ((const uint4*)((split ? g_Alo : g_Ahi) + (m0 + row) * 64))[c4];
        *(uint4*)(sA + split * 32 * 68 + row * 68 + c4 * 4) = v;
    }

    float d[4];
    gemm32_mainloop<2, 68>(tid, g_Wpq[mat], gcta * 64, sA, sB, d);

    const int lane = tid & 31, warp = tid >> 5;
    const int g = lane >> 2, tg = lane & 3;
    const int mtile = warp >> 3, ncolq = warp & 7;
    const int gcol = gcta * 64 + ncolq * 8 + 2 * tg;
    float* dst = (gcol < 256) ? g_P : g_Q;
    const int cc = (gcol < 256) ? gcol : gcol - 256;
    int rlo = m0 + mtile * 16 + g;
    *(float2*)(dst + rlo * 256 + cc)       = make_float2(d[0], d[1]);
    *(float2*)(dst + (rlo + 8) * 256 + cc) = make_float2(d[2], d[3]);
}

// ---------------------------------------------------------------------------
// MLP phase (coalesced scalar layers) + pack x. rows cta*4..+3.
// ---------------------------------------------------------------------------
template<int K1>
__device__ void mlp_phase(int cta, int tid, const float* __restrict__ in,
                          const float* __restrict__ w1, const float* __restrict__ b1,
                          const float* __restrict__ w2, const float* __restrict__ b2,
                          uint32_t* sm)
{
    float* in_s = (float*)sm;          // [4][K1]
    float* hid  = in_s + 4 * K1;       // [4][256]
    float* xs   = hid + 4 * 256;       // [4][128]

    const int row0 = cta * 4;
    for (int idx = tid; idx < 4 * K1; idx += NTHR)
        in_s[idx] = in[row0 * K1 + idx];
    __syncthreads();

    {
        const int pr = tid >> 8, j = tid & 255;
        float acc[2] = {0.f, 0.f};
#pragma unroll 8
        for (int k = 0; k < K1; k++) {
            float w = w1[k * EH + j];
            acc[0] = fmaf(in_s[(pr * 2 + 0) * K1 + k], w, acc[0]);
            acc[1] = fmaf(in_s[(pr * 2 + 1) * K1 + k], w, acc[1]);
        }
        float bb = b1[j];
        hid[(pr * 2 + 0) * 256 + j] = fmaxf(acc[0] + bb, 0.f);
        hid[(pr * 2 + 1) * 256 + j] = fmaxf(acc[1] + bb, 0.f);
    }
    __syncthreads();

    {
        const int rr = tid >> 7, c = tid & 127;
        float acc = 0.f;
#pragma unroll 8
        for (int k = 0; k < EH; k++)
            acc = fmaf(hid[rr * 256 + k], w2[k * NO + c], acc);
        float o = fmaxf(acc + b2[c], 0.f);
        xs[rr * 128 + c] = o;
        g_x[(row0 + rr) * NO + c] = o;
    }
    __syncthreads();

    if (tid < 256) {
        int r = tid >> 6, cp = tid & 63;
        float2 x = *(const float2*)(xs + r * 128 + 2 * cp);
        uint32_t hi, lo;
        bf16split(x.x, x.y, hi, lo);
        g_Ahi[(row0 + r) * 64 + cp] = hi;
        g_Alo[(row0 + r) * 64 + cp] = lo;
    }
}

// ---------------------------------------------------------------------------
// Single persistent kernel.
// ---------------------------------------------------------------------------
__global__ __launch_bounds__(NTHR, 1) void fused_kernel(
    const float* __restrict__ enc_in, const float* __restrict__ dec_in,
    const float* __restrict__ enc_w1, const float* __restrict__ enc_b1,
    const float* __restrict__ enc_w2, const float* __restrict__ enc_b2,
    const float* __restrict__ pe_w1,  const float* __restrict__ pe_b1,
    const float* __restrict__ pe_w2,  const float* __restrict__ pe_b2,
    const float* __restrict__ pn_w1,  const float* __restrict__ pn_b1,
    const float* __restrict__ pn_w2,  const float* __restrict__ pn_b2,
    const float* __restrict__ de_w1,  const float* __restrict__ de_b1,
    const float* __restrict__ de_w2,  const float* __restrict__ de_b2,
    const float* __restrict__ w_hr, const float* __restrict__ w_hi,
    const float* __restrict__ w_hn,
    const float* __restrict__ w_ir, const float* __restrict__ b_ir,
    const float* __restrict__ w_ii, const float* __restrict__ b_ii,
    const float* __restrict__ w_in, const float* __restrict__ b_in,
    float* __restrict__ out, float* __restrict__ state)
{
    extern __shared__ uint32_t sm[];
    const int cta = blockIdx.x;
    const int tid = threadIdx.x;
    unsigned gen = g_bar_gen;

    // ---- phase 0: weight packing into interleaved uint4 format ----
    {
        auto gateval = [&](int k, int c, int gate) -> float {
            if (gate == 0) return (k < 128) ? w_ir[k * 128 + c] : w_hr[(k - 128) * 128 + c];
            if (gate == 1) return (k < 128) ? w_ii[k * 128 + c] : w_hi[(k - 128) * 128 + c];
            if (gate == 2) return (k < 128) ? w_in[k * 128 + c] : 0.f;
            return (k < 128) ? 0.f : w_hn[(k - 128) * 128 + c];
        };
        int gid = cta * NTHR + tid;   // 0..65535
        for (int u = gid; u < 81920; u += GRID * NTHR) {
            if (u < 16384) {
                // edge W2: 2 mats x 8192 uint4
                int mat = u >> 13, rem = u & 8191;
                int ridx = rem >> 7, col = rem & 127;
                int kp = (ridx >> 4) * 32 + ((ridx >> 2) & 3) * 8 + (ridx & 3);
                const float* W = mat ? de_w2 : pe_w2;
                uint32_t h0, l0, h1, l1;
                bf16split(W[(2 * kp) * 128 + col], W[(2 * kp + 1) * 128 + col], h0, l0);
                bf16split(W[(2 * kp + 8) * 128 + col], W[(2 * kp + 9) * 128 + col], h1, l1);
                g_We[mat][rem] = make_uint4(h0, h1, l0, l1);
            } else if (u < 49152) {
                // gates: 32768 uint4; col' = c*4 + gate
                int rem = u - 16384;
                int ridx = rem >> 9, col = rem & 511;
                int kp = (ridx >> 4) * 32 + ((ridx >> 2) & 3) * 8 + (ridx & 3);
                int c = col >> 2, gate = col & 3;
                uint32_t h0, l0, h1, l1;
                bf16split(gateval(2 * kp, c, gate), gateval(2 * kp + 1, c, gate), h0, l0);
                bf16split(gateval(2 * kp + 8, c, gate), gateval(2 * kp + 9, c, gate), h1, l1);
                g_Wg[rem] = make_uint4(h0, h1, l0, l1);
            } else {
                // P/Q: 2 mats x 16384 uint4; cols [P|Q]
                int rem2 = u - 49152;
                int mat = rem2 >> 14, rem = rem2 & 16383;
                int ridx = rem >> 9, col = rem & 511;
                int kp = (ridx >> 4) * 32 + ((ridx >> 2) & 3) * 8 + (ridx & 3);
                const float* W1 = mat ? de_w1 : pe_w1;
                auto pqv = [&](int k) -> float {
                    return (col < 256) ? W1[k * 256 + col] : W1[(128 + k) * 256 + (col - 256)];
                };
                uint32_t h0, l0, h1, l1;
                bf16split(pqv(2 * kp), pqv(2 * kp + 1), h0, l0);
                bf16split(pqv(2 * kp + 8), pqv(2 * kp + 9), h1, l1);
                g_Wpq[mat][rem] = make_uint4(h0, h1, l0, l1);
            }
        }
    }
    grid_sync(gen);

    const int b    = cta >> 3;
    const int gcta = cta & 7;
    unsigned ggen = g_grp_gen[b];

    // ---- encoder mlp1, then P/Q (pe) ----
    mlp_phase<150>(cta, tid, enc_in, enc_w1, enc_b1, enc_w2, enc_b2, sm);
    group_sync(b, ggen);
    pq_phase(b, gcta, tid, 0, sm);
    group_sync(b, ggen);

    // ---- two message-passing rounds ----
    for (int p = 0; p < 2; p++) {
        edge_phase(cta, tid, 0, pe_b1, pe_b2, sm);
        group_sync(b, ggen);
        mlp_phase<128>(cta, tid, g_msg, pn_w1, pn_b1, pn_w2, pn_b2, sm);
        group_sync(b, ggen);
        pq_phase(b, gcta, tid, (p == 0) ? 0 : 1, sm);
        group_sync(b, ggen);
    }

    // ---- decoder: 25 GRU steps, 3 group barriers each ----
    for (int t = 0; t < TSTEPS; t++) {
        edge_phase(cta, tid, 1, de_b1, de_b2, sm);
        group_sync(b, ggen);
        gates_elem_phase(b, gcta, tid, dec_in + (size_t)t * NROWS * 3,
                         w_ir, b_ir, w_ii, b_ii, w_in, b_in,
                         out + (size_t)t * NROWS * NO,
                         (t == TSTEPS - 1) ? state : nullptr, sm);
        group_sync(b, ggen);
        if (t != TSTEPS - 1) {
            pq_phase(b, gcta, tid, 1, sm);
            group_sync(b, ggen);
        }
    }
}

// ---------------------------------------------------------------------------
extern "C" void kernel_launch(void* const* d_in, const int* in_sizes, int n_in,
                              void* d_out, int out_size)
{
    const float* enc_in = (const float*)d_in[0];
    const float* dec_in = (const float*)d_in[1];
    const float* enc_w1 = (const float*)d_in[4];
    const float* enc_b1 = (const float*)d_in[5];
    const float* enc_w2 = (const float*)d_in[6];
    const float* enc_b2 = (const float*)d_in[7];
    const float* pe_w1  = (const float*)d_in[8];
    const float* pe_b1  = (const float*)d_in[9];
    const float* pe_w2  = (const float*)d_in[10];
    const float* pe_b2  = (const float*)d_in[11];
    const float* pn_w1  = (const float*)d_in[12];
    const float* pn_b1  = (const float*)d_in[13];
    const float* pn_w2  = (const float*)d_in[14];
    const float* pn_b2  = (const float*)d_in[15];
    const float* de_w1  = (const float*)d_in[16];
    const float* de_b1  = (const float*)d_in[17];
    const float* de_w2  = (const float*)d_in[18];
    const float* de_b2  = (const float*)d_in[19];
    const float* w_hr   = (const float*)d_in[20];
    const float* w_hi   = (const float*)d_in[21];
    const float* w_hn   = (const float*)d_in[22];
    const float* w_ir   = (const float*)d_in[23];
    const float* b_ir   = (const float*)d_in[24];
    const float* w_ii   = (const float*)d_in[25];
    const float* b_ii   = (const float*)d_in[26];
    const float* w_in   = (const float*)d_in[27];
    const float* b_in   = (const float*)d_in[28];

    float* out   = (float*)d_out;
    float* state = out + (size_t)TSTEPS * NROWS * NO;

    cudaFuncSetAttribute(fused_kernel,
                         cudaFuncAttributeMaxDynamicSharedMemorySize,
                         SMEM_BYTES);

    fused_kernel<<<GRID, NTHR, SMEM_BYTES>>>(
        enc_in, dec_in,
        enc_w1, enc_b1, enc_w2, enc_b2,
        pe_w1, pe_b1, pe_w2, pe_b2,
        pn_w1, pn_b1, pn_w2, pn_b2,
        de_w1, de_b1, de_w2, de_b2,
        w_hr, w_hi, w_hn,
        w_ir, b_ir, w_ii, b_ii, w_in, b_in,
        out, state);
}